// round 1
// baseline (speedup 1.0000x reference)
#include <cuda_runtime.h>
#include <cuda_bf16.h>
#include <math.h>

// Problem constants
#define B_  2
#define T_  2048
#define D_  5120
#define HQ_ 32
#define HK_ 8
#define HD_ 160
#define RD_ 40
#define NTOK (B_ * T_)          // 4096
#define EPS_ 1e-5f

// ---------------------------------------------------------------------------
// Scratch (device globals; no allocations allowed)
// ---------------------------------------------------------------------------
__device__ float g_nx[NTOK * D_];            // normalized input   (4096 x 5120)
__device__ float g_q[NTOK * HQ_ * HD_];      // q                  (4096 x 5120)
__device__ float g_k[NTOK * HK_ * HD_];      // k                  (4096 x 1280)
__device__ float g_v[NTOK * HK_ * HD_];      // v                  (4096 x 1280)
__device__ float g_attn[NTOK * D_];          // attention output   (4096 x 5120)
__device__ float g_cos[T_ * RD_];            // rope cos table
__device__ float g_sin[T_ * RD_];            // rope sin table

// ---------------------------------------------------------------------------
// Kernel 0: RoPE tables in fp64 (tiny)
// ---------------------------------------------------------------------------
__global__ void rope_table_kernel(float* __restrict__ tc, float* __restrict__ ts) {
    int idx = blockIdx.x * 256 + threadIdx.x;
    if (idx >= T_ * RD_) return;
    int t = idx / RD_;
    int i = idx % RD_;
    int f = i % 20;                           // inv_freq index
    double invf = pow(5000000.0, -(double)f / 20.0);
    double ang = (double)t * invf;
    tc[idx] = (float)cos(ang);
    ts[idx] = (float)sin(ang);
}

// ---------------------------------------------------------------------------
// Kernel 1: RMS "layernorm": nx = x * rsqrt(mean(x^2)+eps) * w + b
// one block per token row (D=5120)
// ---------------------------------------------------------------------------
__global__ __launch_bounds__(256) void rmsnorm_kernel(
    const float* __restrict__ x, const float* __restrict__ w,
    const float* __restrict__ b, float* __restrict__ o) {
    int row = blockIdx.x;
    const float4* xr = (const float4*)(x + (size_t)row * D_);
    float ss = 0.f;
    #pragma unroll
    for (int i = threadIdx.x; i < D_ / 4; i += 256) {
        float4 v = xr[i];
        ss += v.x * v.x + v.y * v.y + v.z * v.z + v.w * v.w;
    }
    #pragma unroll
    for (int m = 16; m; m >>= 1) ss += __shfl_xor_sync(0xffffffffu, ss, m);
    __shared__ float red[8];
    if ((threadIdx.x & 31) == 0) red[threadIdx.x >> 5] = ss;
    __syncthreads();
    float tot = 0.f;
    #pragma unroll
    for (int i = 0; i < 8; i++) tot += red[i];
    float r = rsqrtf(tot * (1.0f / (float)D_) + EPS_);

    const float4* w4 = (const float4*)w;
    const float4* b4 = (const float4*)b;
    float4* o4 = (float4*)(o + (size_t)row * D_);
    for (int i = threadIdx.x; i < D_ / 4; i += 256) {
        float4 v = xr[i], ww = w4[i], bb = b4[i];
        float4 out;
        out.x = v.x * r * ww.x + bb.x;
        out.y = v.y * r * ww.y + bb.y;
        out.z = v.z * r * ww.z + bb.z;
        out.w = v.w * r * ww.w + bb.w;
        o4[i] = out;
    }
}

// ---------------------------------------------------------------------------
// Kernel 2: fp32 SGEMM  C[M,N] = A[M,K] @ B[K,N]
// BM=BN=128, BK=8, 256 threads, 8x8 microtile. All dims divide evenly here.
// ---------------------------------------------------------------------------
__global__ __launch_bounds__(256) void sgemm128(
    const float* __restrict__ A, const float* __restrict__ B,
    float* __restrict__ C, int M, int N, int K) {
    __shared__ float As[8][128];
    __shared__ float Bs[8][128];

    int tid = threadIdx.x;
    int tx = tid & 15, ty = tid >> 4;

    const float* Ab = A + (size_t)blockIdx.y * 128 * K;
    const float* Bb = B + (size_t)blockIdx.x * 128;
    float*       Cb = C + (size_t)blockIdx.y * 128 * N + (size_t)blockIdx.x * 128;

    int aRow = tid >> 1;            // 0..127
    int aCol = (tid & 1) << 2;      // 0 or 4
    int bRow = tid >> 5;            // 0..7
    int bCol = (tid & 31) << 2;     // 0..124

    float acc[8][8];
    #pragma unroll
    for (int i = 0; i < 8; i++)
        #pragma unroll
        for (int j = 0; j < 8; j++) acc[i][j] = 0.f;

    for (int k0 = 0; k0 < K; k0 += 8) {
        float4 a4 = *(const float4*)(Ab + (size_t)aRow * K + k0 + aCol);
        float4 b4 = *(const float4*)(Bb + (size_t)(k0 + bRow) * N + bCol);
        As[aCol + 0][aRow] = a4.x;
        As[aCol + 1][aRow] = a4.y;
        As[aCol + 2][aRow] = a4.z;
        As[aCol + 3][aRow] = a4.w;
        *(float4*)&Bs[bRow][bCol] = b4;
        __syncthreads();

        #pragma unroll
        for (int kk = 0; kk < 8; kk++) {
            float4 a0 = *(const float4*)&As[kk][ty * 8];
            float4 a1 = *(const float4*)&As[kk][ty * 8 + 4];
            float4 b0 = *(const float4*)&Bs[kk][tx * 8];
            float4 b1 = *(const float4*)&Bs[kk][tx * 8 + 4];
            float ra[8] = {a0.x, a0.y, a0.z, a0.w, a1.x, a1.y, a1.z, a1.w};
            float rb[8] = {b0.x, b0.y, b0.z, b0.w, b1.x, b1.y, b1.z, b1.w};
            #pragma unroll
            for (int i = 0; i < 8; i++)
                #pragma unroll
                for (int j = 0; j < 8; j++)
                    acc[i][j] = fmaf(ra[i], rb[j], acc[i][j]);
        }
        __syncthreads();
    }

    #pragma unroll
    for (int i = 0; i < 8; i++) {
        #pragma unroll
        for (int j = 0; j < 8; j += 4) {
            *(float4*)(Cb + (size_t)(ty * 8 + i) * N + tx * 8 + j) =
                make_float4(acc[i][j], acc[i][j + 1], acc[i][j + 2], acc[i][j + 3]);
        }
    }
}

// ---------------------------------------------------------------------------
// Kernel 3: per-head RMS norm + partial RoPE (first RD=40 dims).
// One warp per (token, head) row of HD=160. Layout: ((b*T+t)*H + h)*HD + d
// ---------------------------------------------------------------------------
__global__ __launch_bounds__(256) void qknorm_rope_kernel(
    float* __restrict__ q, const float* __restrict__ w, int H,
    const float* __restrict__ tcos, const float* __restrict__ tsin) {
    int row = blockIdx.x * 8 + (threadIdx.x >> 5);
    int lane = threadIdx.x & 31;
    int h = row % H;
    int t = (row / H) & (T_ - 1);

    float* p = q + (size_t)row * HD_;
    float v[5];
    #pragma unroll
    for (int i = 0; i < 5; i++) v[i] = p[lane + 32 * i];
    float ss = 0.f;
    #pragma unroll
    for (int i = 0; i < 5; i++) ss += v[i] * v[i];
    #pragma unroll
    for (int m = 16; m; m >>= 1) ss += __shfl_xor_sync(0xffffffffu, ss, m);
    float r = rsqrtf(ss * (1.0f / (float)HD_) + EPS_);
    const float* wh = w + h * HD_;
    #pragma unroll
    for (int i = 0; i < 5; i++) v[i] *= r * wh[lane + 32 * i];

    // RoPE chunk 0: d = lane (0..31), all rotated. Pair partner = lane^1.
    {
        float partner = __shfl_xor_sync(0xffffffffu, v[0], 1);
        float rot = (lane & 1) ? partner : -partner;
        float c = tcos[t * RD_ + lane];
        float s = tsin[t * RD_ + lane];
        v[0] = v[0] * c + rot * s;
    }
    // RoPE chunk 1: d = 32+lane, rotated only for lane < 8 (d < 40).
    {
        float partner = __shfl_xor_sync(0xffffffffu, v[1], 1);
        if (lane < 8) {
            int d = 32 + lane;
            float rot = (lane & 1) ? partner : -partner;
            v[1] = v[1] * tcos[t * RD_ + d] + rot * tsin[t * RD_ + d];
        }
    }
    #pragma unroll
    for (int i = 0; i < 5; i++) p[lane + 32 * i] = v[i];
}

// ---------------------------------------------------------------------------
// Kernel 4: causal flash attention with GQA (4 q-heads per kv-head).
// BQ=BKV=64, 256 threads. Thread (ty,tx): S microtile 4x4, O microtile 4x10.
// Padded smem strides (161, 65) break the stride-160 bank pathology.
// ---------------------------------------------------------------------------
#define SSTR 161
#define PSTR 65
#define FLASH_SMEM ((3 * 64 * SSTR + 64 * PSTR) * 4)   // 140288 bytes

__global__ __launch_bounds__(256) void flash_kernel(
    const float* __restrict__ Q, const float* __restrict__ K,
    const float* __restrict__ V, float* __restrict__ O) {
    extern __shared__ float sm[];
    float* Qs = sm;                    // 64 x SSTR
    float* Ks = Qs + 64 * SSTR;        // 64 x SSTR
    float* Vs = Ks + 64 * SSTR;        // 64 x SSTR
    float* Ps = Vs + 64 * SSTR;        // 64 x PSTR

    const int qt = blockIdx.x;   // 0..31
    const int h  = blockIdx.y;   // 0..31
    const int b  = blockIdx.z;   // 0..1
    const int hk = h >> 2;
    const int tid = threadIdx.x;
    const int tx = tid & 15, ty = tid >> 4;
    const float scale = 0.07905694150420949f;   // 1/sqrt(160)

    // Load Q tile (64 rows x 160)
    for (int e = tid; e < 64 * 40; e += 256) {
        int rr = e / 40, c4 = (e % 40) * 4;
        float4 v = *(const float4*)(Q + (((size_t)(b * T_ + qt * 64 + rr) * HQ_ + h) * HD_) + c4);
        float* dst = Qs + rr * SSTR + c4;
        dst[0] = v.x; dst[1] = v.y; dst[2] = v.z; dst[3] = v.w;
    }

    float m_i[4], l_i[4], acc[4][10];
    #pragma unroll
    for (int i = 0; i < 4; i++) {
        m_i[i] = -1e30f; l_i[i] = 0.f;
        #pragma unroll
        for (int j = 0; j < 10; j++) acc[i][j] = 0.f;
    }
    __syncthreads();

    for (int kt = 0; kt <= qt; kt++) {
        // load K, V tiles
        for (int e = tid; e < 64 * 40; e += 256) {
            int rr = e / 40, c4 = (e % 40) * 4;
            size_t base = (((size_t)(b * T_ + kt * 64 + rr) * HK_ + hk) * HD_) + c4;
            float4 kv = *(const float4*)(K + base);
            float4 vv = *(const float4*)(V + base);
            float* kd = Ks + rr * SSTR + c4;
            kd[0] = kv.x; kd[1] = kv.y; kd[2] = kv.z; kd[3] = kv.w;
            float* vd = Vs + rr * SSTR + c4;
            vd[0] = vv.x; vd[1] = vv.y; vd[2] = vv.z; vd[3] = vv.w;
        }
        __syncthreads();

        // S = Q @ K^T  (rows ty*4+i, cols tx*4+j)
        float s[4][4];
        #pragma unroll
        for (int i = 0; i < 4; i++)
            #pragma unroll
            for (int j = 0; j < 4; j++) s[i][j] = 0.f;

        const float* qb0 = Qs + (ty * 4) * SSTR;
        const float* kb0 = Ks + (tx * 4) * SSTR;
        #pragma unroll 4
        for (int d = 0; d < HD_; d++) {
            float qa[4], kb[4];
            #pragma unroll
            for (int i = 0; i < 4; i++) qa[i] = qb0[i * SSTR + d];
            #pragma unroll
            for (int j = 0; j < 4; j++) kb[j] = kb0[j * SSTR + d];
            #pragma unroll
            for (int i = 0; i < 4; i++)
                #pragma unroll
                for (int j = 0; j < 4; j++)
                    s[i][j] = fmaf(qa[i], kb[j], s[i][j]);
        }

        // scale + causal mask
        if (kt == qt) {
            #pragma unroll
            for (int i = 0; i < 4; i++)
                #pragma unroll
                for (int j = 0; j < 4; j++)
                    s[i][j] = (tx * 4 + j > ty * 4 + i) ? -1e30f : s[i][j] * scale;
        } else {
            #pragma unroll
            for (int i = 0; i < 4; i++)
                #pragma unroll
                for (int j = 0; j < 4; j++) s[i][j] *= scale;
        }

        // online softmax per row (reduce across the 16 tx lanes via xor<=8)
        #pragma unroll
        for (int i = 0; i < 4; i++) {
            float mx = fmaxf(fmaxf(s[i][0], s[i][1]), fmaxf(s[i][2], s[i][3]));
            #pragma unroll
            for (int o = 8; o; o >>= 1) mx = fmaxf(mx, __shfl_xor_sync(0xffffffffu, mx, o));
            float mn = fmaxf(m_i[i], mx);
            float alpha = __expf(m_i[i] - mn);
            m_i[i] = mn;
            float rs = 0.f;
            #pragma unroll
            for (int j = 0; j < 4; j++) {
                s[i][j] = __expf(s[i][j] - mn);
                rs += s[i][j];
            }
            #pragma unroll
            for (int o = 8; o; o >>= 1) rs += __shfl_xor_sync(0xffffffffu, rs, o);
            l_i[i] = l_i[i] * alpha + rs;
            #pragma unroll
            for (int jj = 0; jj < 10; jj++) acc[i][jj] *= alpha;
            #pragma unroll
            for (int j = 0; j < 4; j++)
                Ps[(ty * 4 + i) * PSTR + tx * 4 + j] = s[i][j];
        }
        __syncthreads();

        // O += P @ V   (rows ty*4+i, cols tx*10+jj)
        #pragma unroll 2
        for (int kk = 0; kk < 64; kk++) {
            float pv[4];
            #pragma unroll
            for (int i = 0; i < 4; i++) pv[i] = Ps[(ty * 4 + i) * PSTR + kk];
            float vv[10];
            #pragma unroll
            for (int jj = 0; jj < 10; jj++) vv[jj] = Vs[kk * SSTR + tx * 10 + jj];
            #pragma unroll
            for (int i = 0; i < 4; i++)
                #pragma unroll
                for (int jj = 0; jj < 10; jj++)
                    acc[i][jj] = fmaf(pv[i], vv[jj], acc[i][jj]);
        }
        __syncthreads();
    }

    // write O (normalize by l)
    #pragma unroll
    for (int i = 0; i < 4; i++) {
        float inv = 1.0f / l_i[i];
        int r = qt * 64 + ty * 4 + i;
        float* dst = O + (((size_t)(b * T_ + r) * HQ_ + h) * HD_) + tx * 10;
        #pragma unroll
        for (int jj = 0; jj < 10; jj++) dst[jj] = acc[i][jj] * inv;
    }
}

// ---------------------------------------------------------------------------
// Host launch
// ---------------------------------------------------------------------------
extern "C" void kernel_launch(void* const* d_in, const int* in_sizes, int n_in,
                              void* d_out, int out_size) {
    const float* x      = (const float*)d_in[0];
    const float* wq     = (const float*)d_in[1];
    const float* wk     = (const float*)d_in[2];
    const float* wv     = (const float*)d_in[3];
    const float* wo     = (const float*)d_in[4];
    const float* norm_w = (const float*)d_in[5];
    const float* norm_b = (const float*)d_in[6];
    const float* qn_w   = (const float*)d_in[7];
    const float* kn_w   = (const float*)d_in[8];
    float* out = (float*)d_out;

    float *nx, *q, *k, *v, *attn, *tcos, *tsin;
    cudaGetSymbolAddress((void**)&nx,   g_nx);
    cudaGetSymbolAddress((void**)&q,    g_q);
    cudaGetSymbolAddress((void**)&k,    g_k);
    cudaGetSymbolAddress((void**)&v,    g_v);
    cudaGetSymbolAddress((void**)&attn, g_attn);
    cudaGetSymbolAddress((void**)&tcos, g_cos);
    cudaGetSymbolAddress((void**)&tsin, g_sin);

    cudaFuncSetAttribute(flash_kernel, cudaFuncAttributeMaxDynamicSharedMemorySize,
                         FLASH_SMEM);

    // 0. rope tables
    rope_table_kernel<<<(T_ * RD_ + 255) / 256, 256>>>(tcos, tsin);
    // 1. RMS layernorm
    rmsnorm_kernel<<<NTOK, 256>>>(x, norm_w, norm_b, nx);
    // 2-4. projections
    sgemm128<<<dim3(D_ / 128, NTOK / 128), 256>>>(nx, wq, q, NTOK, HQ_ * HD_, D_);
    sgemm128<<<dim3((HK_ * HD_) / 128, NTOK / 128), 256>>>(nx, wk, k, NTOK, HK_ * HD_, D_);
    sgemm128<<<dim3((HK_ * HD_) / 128, NTOK / 128), 256>>>(nx, wv, v, NTOK, HK_ * HD_, D_);
    // 5-6. per-head norm + rope
    qknorm_rope_kernel<<<(NTOK * HQ_) / 8, 256>>>(q, qn_w, HQ_, tcos, tsin);
    qknorm_rope_kernel<<<(NTOK * HK_) / 8, 256>>>(k, kn_w, HK_, tcos, tsin);
    // 7. attention
    flash_kernel<<<dim3(T_ / 64, HQ_, B_), 256, FLASH_SMEM>>>(q, k, v, attn);
    // 8. output projection
    sgemm128<<<dim3(D_ / 128, NTOK / 128), 256>>>(attn, wo, out, NTOK, D_, D_);
}

// round 3
// speedup vs baseline: 2.2178x; 2.2178x over previous
#include <cuda_runtime.h>
#include <cuda_bf16.h>
#include <math.h>
#include <cstdint>

// Problem constants
#define B_  2
#define T_  2048
#define D_  5120
#define HQ_ 32
#define HK_ 8
#define HD_ 160
#define RD_ 40
#define NTOK (B_ * T_)          // 4096
#define EPS_ 1e-5f
#define NQKV 7680               // 5120 + 1280 + 1280
#define KOFF 5120
#define VOFF 6400

// ---------------------------------------------------------------------------
// PTX helpers (generic sm_80+ subset: mma.sync / ldmatrix / cp.async)
// ---------------------------------------------------------------------------
__device__ __forceinline__ uint32_t smem_u32(const void* p) {
    uint32_t a;
    asm("{ .reg .u64 t; cvta.to.shared.u64 t, %1; cvt.u32.u64 %0, t; }" : "=r"(a) : "l"(p));
    return a;
}
__device__ __forceinline__ void cp16(uint32_t s, const void* g) {
    asm volatile("cp.async.cg.shared.global [%0], [%1], 16;" :: "r"(s), "l"(g));
}
#define CP_COMMIT() asm volatile("cp.async.commit_group;")
#define CP_WAIT0()  asm volatile("cp.async.wait_group 0;")
#define CP_WAIT1()  asm volatile("cp.async.wait_group 1;")

__device__ __forceinline__ void ldm4(uint32_t* r, uint32_t addr) {
    asm volatile("ldmatrix.sync.aligned.m8n8.x4.shared.b16 {%0,%1,%2,%3}, [%4];"
                 : "=r"(r[0]), "=r"(r[1]), "=r"(r[2]), "=r"(r[3]) : "r"(addr));
}
__device__ __forceinline__ void mma_bf16(float* c, const uint32_t* a, const uint32_t* b) {
    asm volatile(
        "mma.sync.aligned.m16n8k16.row.col.f32.bf16.bf16.f32 "
        "{%0,%1,%2,%3}, {%4,%5,%6,%7}, {%8,%9}, {%0,%1,%2,%3};"
        : "+f"(c[0]), "+f"(c[1]), "+f"(c[2]), "+f"(c[3])
        : "r"(a[0]), "r"(a[1]), "r"(a[2]), "r"(a[3]), "r"(b[0]), "r"(b[1]));
}

__device__ __forceinline__ void split2(float v, __nv_bfloat16& h, __nv_bfloat16& l) {
    h = __float2bfloat16(v);
    l = __float2bfloat16(v - __bfloat162float(h));
}

// ---------------------------------------------------------------------------
// Scratch (device globals)
// ---------------------------------------------------------------------------
__device__ __nv_bfloat16 g_ah[NTOK * D_];        // nx hi
__device__ __nv_bfloat16 g_al[NTOK * D_];        // nx lo
__device__ __nv_bfloat16 g_wth[NQKV * D_];       // [wq|wk|wv]^T hi  [7680,5120]
__device__ __nv_bfloat16 g_wtl[NQKV * D_];
__device__ __nv_bfloat16 g_woh[D_ * D_];         // wo^T hi [5120,5120]
__device__ __nv_bfloat16 g_wol[D_ * D_];
__device__ float g_qkv[NTOK * NQKV];             // fused qkv output (fp32)
__device__ __nv_bfloat16 g_oh[NTOK * D_];        // attn out hi
__device__ __nv_bfloat16 g_ol[NTOK * D_];        // attn out lo
__device__ float g_cos[T_ * RD_];
__device__ float g_sin[T_ * RD_];

// ---------------------------------------------------------------------------
// Kernel 0: RoPE tables (fp64)
// ---------------------------------------------------------------------------
__global__ void rope_table_kernel(float* __restrict__ tc, float* __restrict__ ts) {
    int idx = blockIdx.x * 256 + threadIdx.x;
    if (idx >= T_ * RD_) return;
    int t = idx / RD_;
    int i = idx % RD_;
    int f = i % 20;
    double invf = pow(5000000.0, -(double)f / 20.0);
    double ang = (double)t * invf;
    tc[idx] = (float)cos(ang);
    ts[idx] = (float)sin(ang);
}

// ---------------------------------------------------------------------------
// Kernel 1: weight transpose + bf16 split: dst[n0+n][k] = split(src[k][n])
// ---------------------------------------------------------------------------
__global__ __launch_bounds__(256) void wsplit_t(
    const float* __restrict__ src, __nv_bfloat16* __restrict__ dh,
    __nv_bfloat16* __restrict__ dl, int N, int Kdim, int n0) {
    __shared__ float tile[32][33];
    int kb = blockIdx.y * 32, nb = blockIdx.x * 32;
    int tx = threadIdx.x & 31, ty = threadIdx.x >> 5;
    #pragma unroll
    for (int i = 0; i < 4; i++)
        tile[ty + i * 8][tx] = src[(size_t)(kb + ty + i * 8) * N + nb + tx];
    __syncthreads();
    #pragma unroll
    for (int i = 0; i < 4; i++) {
        int r = ty + i * 8;
        float v = tile[tx][r];
        __nv_bfloat16 h, l;
        split2(v, h, l);
        size_t o = (size_t)(n0 + nb + r) * Kdim + kb + tx;
        dh[o] = h; dl[o] = l;
    }
}

// ---------------------------------------------------------------------------
// Kernel 2: RMS layernorm -> bf16 hi/lo
// ---------------------------------------------------------------------------
__global__ __launch_bounds__(256) void rmsnorm_kernel(
    const float* __restrict__ x, const float* __restrict__ w,
    const float* __restrict__ b, __nv_bfloat16* __restrict__ oh,
    __nv_bfloat16* __restrict__ ol) {
    int row = blockIdx.x;
    const float4* xr = (const float4*)(x + (size_t)row * D_);
    float ss = 0.f;
    #pragma unroll
    for (int i = threadIdx.x; i < D_ / 4; i += 256) {
        float4 v = xr[i];
        ss += v.x * v.x + v.y * v.y + v.z * v.z + v.w * v.w;
    }
    #pragma unroll
    for (int m = 16; m; m >>= 1) ss += __shfl_xor_sync(0xffffffffu, ss, m);
    __shared__ float red[8];
    if ((threadIdx.x & 31) == 0) red[threadIdx.x >> 5] = ss;
    __syncthreads();
    float tot = 0.f;
    #pragma unroll
    for (int i = 0; i < 8; i++) tot += red[i];
    float r = rsqrtf(tot * (1.0f / (float)D_) + EPS_);

    const float4* w4 = (const float4*)w;
    const float4* b4 = (const float4*)b;
    for (int i = threadIdx.x; i < D_ / 4; i += 256) {
        float4 v = xr[i], ww = w4[i], bb = b4[i];
        float o0 = v.x * r * ww.x + bb.x;
        float o1 = v.y * r * ww.y + bb.y;
        float o2 = v.z * r * ww.z + bb.z;
        float o3 = v.w * r * ww.w + bb.w;
        __nv_bfloat16 h0, l0, h1, l1, h2, l2, h3, l3;
        split2(o0, h0, l0); split2(o1, h1, l1);
        split2(o2, h2, l2); split2(o3, h3, l3);
        size_t base = (size_t)row * D_ + i * 4;
        *(__nv_bfloat162*)(oh + base)     = __nv_bfloat162(h0, h1);
        *(__nv_bfloat162*)(oh + base + 2) = __nv_bfloat162(h2, h3);
        *(__nv_bfloat162*)(ol + base)     = __nv_bfloat162(l0, l1);
        *(__nv_bfloat162*)(ol + base + 2) = __nv_bfloat162(l2, l3);
    }
}

// ---------------------------------------------------------------------------
// Kernel 3: HMMA GEMM, C[M,N] = (Ah+Al)[M,K] @ (Bh+Bl)[N,K]^T  (bf16 x3)
// BM=128, BN=256, BK=32, 512 threads, warp grid 2x8 (64x32 warp tiles),
// 2-stage cp.async double buffer, padded smem stride 40.
// ---------------------------------------------------------------------------
#define BM 128
#define BN 256
#define BK 32
#define PAD 40
#define ATILE (BM * PAD * 2)                 // 10240 B
#define BTILE (BN * PAD * 2)                 // 20480 B
#define BUFSZ (2 * ATILE + 2 * BTILE)        // 61440 B
#define GEMM_SMEM (2 * BUFSZ)                // 122880 B

__global__ __launch_bounds__(512, 1) void hmma_gemm(
    const __nv_bfloat16* __restrict__ Ah, const __nv_bfloat16* __restrict__ Al,
    const __nv_bfloat16* __restrict__ Bh, const __nv_bfloat16* __restrict__ Bl,
    float* __restrict__ C, int Kdim, int Nstride) {
    extern __shared__ char sm[];
    uint32_t smb = smem_u32(sm);
    const int tid = threadIdx.x;
    const int lane = tid & 31, wid = tid >> 5;
    const int wm = (wid >> 3) * 64;          // 0 or 64
    const int wn = (wid & 7) * 32;           // 0..224

    const size_t mBase = (size_t)blockIdx.y * BM;
    const size_t nBase = (size_t)blockIdx.x * BN;
    const __nv_bfloat16* Ag[2] = {Ah + mBase * Kdim, Al + mBase * Kdim};
    const __nv_bfloat16* Bg[2] = {Bh + nBase * Kdim, Bl + nBase * Kdim};

    // --- tile loader: 3072 x 16B chunks, 6 per thread ---
    auto load_tiles = [&](int buf, int kc) {
        uint32_t base = smb + buf * BUFSZ;
        #pragma unroll
        for (int j = 0; j < 6; j++) {
            int c = tid + j * 512;
            const __nv_bfloat16* src;
            uint32_t soff;
            int cc;
            if (c < 1024) {                  // A tiles: 512 chunks each
                int hl = c >> 9; cc = c & 511;
                src = Ag[hl]; soff = base + hl * ATILE;
            } else {                         // B tiles: 1024 chunks each
                int c2 = c - 1024;
                int hl = c2 >> 10; cc = c2 & 1023;
                src = Bg[hl]; soff = base + 2 * ATILE + hl * BTILE;
            }
            int row = cc >> 2, col = (cc & 3) << 3;
            cp16(soff + (row * PAD + col) * 2,
                 src + (size_t)row * Kdim + kc + col);
        }
    };

    float acc[4][4][4];
    #pragma unroll
    for (int i = 0; i < 4; i++)
        #pragma unroll
        for (int j = 0; j < 4; j++)
            #pragma unroll
            for (int e = 0; e < 4; e++) acc[i][j][e] = 0.f;

    // ldmatrix lane addressing
    const int t8 = lane >> 3, r8 = lane & 7;
    const int aRow = wm + r8 + ((t8 & 1) << 3);
    const int aCol = (t8 >> 1) << 3;
    const int bRow = wn + r8 + ((t8 >> 1) << 3);
    const int bCol = (t8 & 1) << 3;

    const int KITERS = Kdim / BK;
    load_tiles(0, 0);
    CP_COMMIT();

    for (int it = 0; it < KITERS; ++it) {
        if (it + 1 < KITERS) {
            load_tiles((it + 1) & 1, (it + 1) * BK);
            CP_COMMIT();
            CP_WAIT1();
        } else {
            CP_WAIT0();
        }
        __syncthreads();

        uint32_t base = smb + (it & 1) * BUFSZ;
        uint32_t sAh = base, sAl = base + ATILE;
        uint32_t sBh = base + 2 * ATILE, sBl = sBh + BTILE;

        #pragma unroll
        for (int ks = 0; ks < 2; ks++) {
            int k0 = ks << 4;
            uint32_t ah[4][4];
            #pragma unroll
            for (int mf = 0; mf < 4; mf++)
                ldm4(ah[mf], sAh + ((aRow + mf * 16) * PAD + k0 + aCol) * 2);
            uint32_t bh[4][2];
            #pragma unroll
            for (int nf2 = 0; nf2 < 2; nf2++) {
                uint32_t r[4];
                ldm4(r, sBh + ((bRow + nf2 * 16) * PAD + k0 + bCol) * 2);
                bh[nf2 * 2][0] = r[0]; bh[nf2 * 2][1] = r[1];
                bh[nf2 * 2 + 1][0] = r[2]; bh[nf2 * 2 + 1][1] = r[3];
            }
            #pragma unroll
            for (int mf = 0; mf < 4; mf++)
                #pragma unroll
                for (int nf = 0; nf < 4; nf++)
                    mma_bf16(acc[mf][nf], ah[mf], bh[nf]);

            uint32_t bl[4][2];
            #pragma unroll
            for (int nf2 = 0; nf2 < 2; nf2++) {
                uint32_t r[4];
                ldm4(r, sBl + ((bRow + nf2 * 16) * PAD + k0 + bCol) * 2);
                bl[nf2 * 2][0] = r[0]; bl[nf2 * 2][1] = r[1];
                bl[nf2 * 2 + 1][0] = r[2]; bl[nf2 * 2 + 1][1] = r[3];
            }
            #pragma unroll
            for (int mf = 0; mf < 4; mf++)
                #pragma unroll
                for (int nf = 0; nf < 4; nf++)
                    mma_bf16(acc[mf][nf], ah[mf], bl[nf]);

            uint32_t al[4][4];
            #pragma unroll
            for (int mf = 0; mf < 4; mf++)
                ldm4(al[mf], sAl + ((aRow + mf * 16) * PAD + k0 + aCol) * 2);
            #pragma unroll
            for (int mf = 0; mf < 4; mf++)
                #pragma unroll
                for (int nf = 0; nf < 4; nf++)
                    mma_bf16(acc[mf][nf], al[mf], bh[nf]);
        }
        __syncthreads();
    }

    // epilogue: direct fp32 stores
    float* Cb = C + (mBase + wm) * Nstride + nBase + wn;
    const int er = lane >> 2, ec = (lane & 3) * 2;
    #pragma unroll
    for (int mf = 0; mf < 4; mf++) {
        #pragma unroll
        for (int nf = 0; nf < 4; nf++) {
            float* p0 = Cb + (size_t)(mf * 16 + er) * Nstride + nf * 8 + ec;
            p0[0] = acc[mf][nf][0];
            p0[1] = acc[mf][nf][1];
            float* p1 = p0 + 8 * (size_t)Nstride;
            p1[0] = acc[mf][nf][2];
            p1[1] = acc[mf][nf][3];
        }
    }
}

// ---------------------------------------------------------------------------
// Kernel 4: per-head RMS norm + partial RoPE, in-place on qkv buffer.
// ---------------------------------------------------------------------------
__global__ __launch_bounds__(256) void qknorm_rope_kernel(
    float* __restrict__ base, const float* __restrict__ w, int H,
    const float* __restrict__ tcos, const float* __restrict__ tsin) {
    int rowi = blockIdx.x * 8 + (threadIdx.x >> 5);
    int lane = threadIdx.x & 31;
    int h = rowi % H;
    int tok = rowi / H;
    int t = tok & (T_ - 1);

    float* p = base + (size_t)tok * NQKV + h * HD_;
    float v[5];
    #pragma unroll
    for (int i = 0; i < 5; i++) v[i] = p[lane + 32 * i];
    float ss = 0.f;
    #pragma unroll
    for (int i = 0; i < 5; i++) ss += v[i] * v[i];
    #pragma unroll
    for (int m = 16; m; m >>= 1) ss += __shfl_xor_sync(0xffffffffu, ss, m);
    float r = rsqrtf(ss * (1.0f / (float)HD_) + EPS_);
    const float* wh = w + h * HD_;
    #pragma unroll
    for (int i = 0; i < 5; i++) v[i] *= r * wh[lane + 32 * i];

    {   // RoPE d = lane (0..31)
        float partner = __shfl_xor_sync(0xffffffffu, v[0], 1);
        float rot = (lane & 1) ? partner : -partner;
        v[0] = v[0] * tcos[t * RD_ + lane] + rot * tsin[t * RD_ + lane];
    }
    {   // RoPE d = 32..39
        float partner = __shfl_xor_sync(0xffffffffu, v[1], 1);
        if (lane < 8) {
            int d = 32 + lane;
            float rot = (lane & 1) ? partner : -partner;
            v[1] = v[1] * tcos[t * RD_ + d] + rot * tsin[t * RD_ + d];
        }
    }
    #pragma unroll
    for (int i = 0; i < 5; i++) p[lane + 32 * i] = v[i];
}

// ---------------------------------------------------------------------------
// Kernel 5: causal flash attention (fp32), GQA 4:1. BQ=BKV=64, 256 threads.
// Reads fused qkv buffer; writes bf16 hi/lo attn output.
// ---------------------------------------------------------------------------
#define SSTR 161
#define PSTR 65
#define FLASH_SMEM ((3 * 64 * SSTR + 64 * PSTR) * 4)

__global__ __launch_bounds__(256) void flash_kernel(
    const float* __restrict__ QKV, __nv_bfloat16* __restrict__ Oh,
    __nv_bfloat16* __restrict__ Ol) {
    extern __shared__ float smf[];
    float* Qs = smf;
    float* Ks = Qs + 64 * SSTR;
    float* Vs = Ks + 64 * SSTR;
    float* Ps = Vs + 64 * SSTR;

    const int qt = blockIdx.x;
    const int h  = blockIdx.y;
    const int b  = blockIdx.z;
    const int hk = h >> 2;
    const int tid = threadIdx.x;
    const int tx = tid & 15, ty = tid >> 4;
    const float scale = 0.07905694150420949f;

    for (int e = tid; e < 64 * 40; e += 256) {
        int rr = e / 40, c4 = (e % 40) * 4;
        float4 v = *(const float4*)(QKV + (size_t)(b * T_ + qt * 64 + rr) * NQKV + h * HD_ + c4);
        float* dst = Qs + rr * SSTR + c4;
        dst[0] = v.x; dst[1] = v.y; dst[2] = v.z; dst[3] = v.w;
    }

    float m_i[4], l_i[4], acc[4][10];
    #pragma unroll
    for (int i = 0; i < 4; i++) {
        m_i[i] = -1e30f; l_i[i] = 0.f;
        #pragma unroll
        for (int j = 0; j < 10; j++) acc[i][j] = 0.f;
    }
    __syncthreads();

    for (int kt = 0; kt <= qt; kt++) {
        for (int e = tid; e < 64 * 40; e += 256) {
            int rr = e / 40, c4 = (e % 40) * 4;
            size_t rb = (size_t)(b * T_ + kt * 64 + rr) * NQKV + hk * HD_ + c4;
            float4 kv = *(const float4*)(QKV + rb + KOFF);
            float4 vv = *(const float4*)(QKV + rb + VOFF);
            float* kd = Ks + rr * SSTR + c4;
            kd[0] = kv.x; kd[1] = kv.y; kd[2] = kv.z; kd[3] = kv.w;
            float* vd = Vs + rr * SSTR + c4;
            vd[0] = vv.x; vd[1] = vv.y; vd[2] = vv.z; vd[3] = vv.w;
        }
        __syncthreads();

        float s[4][4];
        #pragma unroll
        for (int i = 0; i < 4; i++)
            #pragma unroll
            for (int j = 0; j < 4; j++) s[i][j] = 0.f;

        const float* qb0 = Qs + (ty * 4) * SSTR;
        const float* kb0 = Ks + (tx * 4) * SSTR;
        #pragma unroll 4
        for (int d = 0; d < HD_; d++) {
            float qa[4], kb[4];
            #pragma unroll
            for (int i = 0; i < 4; i++) qa[i] = qb0[i * SSTR + d];
            #pragma unroll
            for (int j = 0; j < 4; j++) kb[j] = kb0[j * SSTR + d];
            #pragma unroll
            for (int i = 0; i < 4; i++)
                #pragma unroll
                for (int j = 0; j < 4; j++)
                    s[i][j] = fmaf(qa[i], kb[j], s[i][j]);
        }

        if (kt == qt) {
            #pragma unroll
            for (int i = 0; i < 4; i++)
                #pragma unroll
                for (int j = 0; j < 4; j++)
                    s[i][j] = (tx * 4 + j > ty * 4 + i) ? -1e30f : s[i][j] * scale;
        } else {
            #pragma unroll
            for (int i = 0; i < 4; i++)
                #pragma unroll
                for (int j = 0; j < 4; j++) s[i][j] *= scale;
        }

        #pragma unroll
        for (int i = 0; i < 4; i++) {
            float mx = fmaxf(fmaxf(s[i][0], s[i][1]), fmaxf(s[i][2], s[i][3]));
            #pragma unroll
            for (int o = 8; o; o >>= 1) mx = fmaxf(mx, __shfl_xor_sync(0xffffffffu, mx, o));
            float mn = fmaxf(m_i[i], mx);
            float alpha = __expf(m_i[i] - mn);
            m_i[i] = mn;
            float rs = 0.f;
            #pragma unroll
            for (int j = 0; j < 4; j++) {
                s[i][j] = __expf(s[i][j] - mn);
                rs += s[i][j];
            }
            #pragma unroll
            for (int o = 8; o; o >>= 1) rs += __shfl_xor_sync(0xffffffffu, rs, o);
            l_i[i] = l_i[i] * alpha + rs;
            #pragma unroll
            for (int jj = 0; jj < 10; jj++) acc[i][jj] *= alpha;
            #pragma unroll
            for (int j = 0; j < 4; j++)
                Ps[(ty * 4 + i) * PSTR + tx * 4 + j] = s[i][j];
        }
        __syncthreads();

        #pragma unroll 2
        for (int kk = 0; kk < 64; kk++) {
            float pv[4];
            #pragma unroll
            for (int i = 0; i < 4; i++) pv[i] = Ps[(ty * 4 + i) * PSTR + kk];
            float vv[10];
            #pragma unroll
            for (int jj = 0; jj < 10; jj++) vv[jj] = Vs[kk * SSTR + tx * 10 + jj];
            #pragma unroll
            for (int i = 0; i < 4; i++)
                #pragma unroll
                for (int jj = 0; jj < 10; jj++)
                    acc[i][jj] = fmaf(pv[i], vv[jj], acc[i][jj]);
        }
        __syncthreads();
    }

    #pragma unroll
    for (int i = 0; i < 4; i++) {
        float inv = 1.0f / l_i[i];
        int r = qt * 64 + ty * 4 + i;
        size_t base = (size_t)(b * T_ + r) * D_ + h * HD_ + tx * 10;
        #pragma unroll
        for (int jj = 0; jj < 10; jj++) {
            float val = acc[i][jj] * inv;
            __nv_bfloat16 hh, ll;
            split2(val, hh, ll);
            Oh[base + jj] = hh;
            Ol[base + jj] = ll;
        }
    }
}

// ---------------------------------------------------------------------------
// Host launch
// ---------------------------------------------------------------------------
extern "C" void kernel_launch(void* const* d_in, const int* in_sizes, int n_in,
                              void* d_out, int out_size) {
    const float* x      = (const float*)d_in[0];
    const float* wq     = (const float*)d_in[1];
    const float* wk     = (const float*)d_in[2];
    const float* wv     = (const float*)d_in[3];
    const float* wo     = (const float*)d_in[4];
    const float* norm_w = (const float*)d_in[5];
    const float* norm_b = (const float*)d_in[6];
    const float* qn_w   = (const float*)d_in[7];
    const float* kn_w   = (const float*)d_in[8];
    float* out = (float*)d_out;

    __nv_bfloat16 *ah, *al, *wth, *wtl, *woh, *wol, *oh, *ol;
    float *qkv, *tcos, *tsin;
    cudaGetSymbolAddress((void**)&ah,   g_ah);
    cudaGetSymbolAddress((void**)&al,   g_al);
    cudaGetSymbolAddress((void**)&wth,  g_wth);
    cudaGetSymbolAddress((void**)&wtl,  g_wtl);
    cudaGetSymbolAddress((void**)&woh,  g_woh);
    cudaGetSymbolAddress((void**)&wol,  g_wol);
    cudaGetSymbolAddress((void**)&oh,   g_oh);
    cudaGetSymbolAddress((void**)&ol,   g_ol);
    cudaGetSymbolAddress((void**)&qkv,  g_qkv);
    cudaGetSymbolAddress((void**)&tcos, g_cos);
    cudaGetSymbolAddress((void**)&tsin, g_sin);

    cudaFuncSetAttribute(flash_kernel, cudaFuncAttributeMaxDynamicSharedMemorySize, FLASH_SMEM);
    cudaFuncSetAttribute(hmma_gemm, cudaFuncAttributeMaxDynamicSharedMemorySize, GEMM_SMEM);

    // 0. rope tables
    rope_table_kernel<<<(T_ * RD_ + 255) / 256, 256>>>(tcos, tsin);
    // 1. weight transpose + split
    wsplit_t<<<dim3(D_ / 32, D_ / 32), 256>>>(wq, wth, wtl, D_, D_, 0);
    wsplit_t<<<dim3((HK_ * HD_) / 32, D_ / 32), 256>>>(wk, wth, wtl, HK_ * HD_, D_, KOFF);
    wsplit_t<<<dim3((HK_ * HD_) / 32, D_ / 32), 256>>>(wv, wth, wtl, HK_ * HD_, D_, VOFF);
    wsplit_t<<<dim3(D_ / 32, D_ / 32), 256>>>(wo, woh, wol, D_, D_, 0);
    // 2. RMS layernorm -> bf16 hi/lo
    rmsnorm_kernel<<<NTOK, 256>>>(x, norm_w, norm_b, ah, al);
    // 3. fused QKV projection (HMMA bf16 x3)
    hmma_gemm<<<dim3(NQKV / BN, NTOK / BM), 512, GEMM_SMEM>>>(
        ah, al, wth, wtl, qkv, D_, NQKV);
    // 4. per-head norm + rope (in place on qkv)
    qknorm_rope_kernel<<<(NTOK * HQ_) / 8, 256>>>(qkv, qn_w, HQ_, tcos, tsin);
    qknorm_rope_kernel<<<(NTOK * HK_) / 8, 256>>>(qkv + KOFF, kn_w, HK_, tcos, tsin);
    // 5. attention
    flash_kernel<<<dim3(T_ / 64, HQ_, B_), 256, FLASH_SMEM>>>(qkv, oh, ol);
    // 6. output projection (HMMA bf16 x3)
    hmma_gemm<<<dim3(D_ / BN, NTOK / BM), 512, GEMM_SMEM>>>(
        oh, ol, woh, wol, out, D_, D_);
}

// round 4
// speedup vs baseline: 3.0526x; 1.3764x over previous
#include <cuda_runtime.h>
#include <cuda_bf16.h>
#include <math.h>
#include <cstdint>

// Problem constants
#define B_  2
#define T_  2048
#define D_  5120
#define HQ_ 32
#define HK_ 8
#define HD_ 160
#define RD_ 40
#define NTOK (B_ * T_)          // 4096
#define EPS_ 1e-5f
#define NQKV 7680               // 5120 + 1280 + 1280
#define KOFF 5120
#define VOFF 6400

// ---------------------------------------------------------------------------
// PTX helpers (generic sm_80+ subset: mma.sync / ldmatrix / cp.async)
// ---------------------------------------------------------------------------
__device__ __forceinline__ uint32_t smem_u32(const void* p) {
    uint32_t a;
    asm("{ .reg .u64 t; cvta.to.shared.u64 t, %1; cvt.u32.u64 %0, t; }" : "=r"(a) : "l"(p));
    return a;
}
__device__ __forceinline__ void cp16(uint32_t s, const void* g) {
    asm volatile("cp.async.cg.shared.global [%0], [%1], 16;" :: "r"(s), "l"(g));
}
#define CP_COMMIT() asm volatile("cp.async.commit_group;")
#define CP_WAIT0()  asm volatile("cp.async.wait_group 0;")
#define CP_WAIT1()  asm volatile("cp.async.wait_group 1;")

__device__ __forceinline__ void ldm4(uint32_t* r, uint32_t addr) {
    asm volatile("ldmatrix.sync.aligned.m8n8.x4.shared.b16 {%0,%1,%2,%3}, [%4];"
                 : "=r"(r[0]), "=r"(r[1]), "=r"(r[2]), "=r"(r[3]) : "r"(addr));
}
__device__ __forceinline__ void ldm4t(uint32_t* r, uint32_t addr) {
    asm volatile("ldmatrix.sync.aligned.m8n8.x4.trans.shared.b16 {%0,%1,%2,%3}, [%4];"
                 : "=r"(r[0]), "=r"(r[1]), "=r"(r[2]), "=r"(r[3]) : "r"(addr));
}
__device__ __forceinline__ void mma_bf16(float* c, const uint32_t* a, const uint32_t* b) {
    asm volatile(
        "mma.sync.aligned.m16n8k16.row.col.f32.bf16.bf16.f32 "
        "{%0,%1,%2,%3}, {%4,%5,%6,%7}, {%8,%9}, {%0,%1,%2,%3};"
        : "+f"(c[0]), "+f"(c[1]), "+f"(c[2]), "+f"(c[3])
        : "r"(a[0]), "r"(a[1]), "r"(a[2]), "r"(a[3]), "r"(b[0]), "r"(b[1]));
}

__device__ __forceinline__ void split2(float v, __nv_bfloat16& h, __nv_bfloat16& l) {
    h = __float2bfloat16(v);
    l = __float2bfloat16(v - __bfloat162float(h));
}
// pack pair of floats -> bf16x2 hi frag and lo frag
__device__ __forceinline__ void packhl(float a, float b, uint32_t& hi, uint32_t& lo) {
    __nv_bfloat162 h2 = __floats2bfloat162_rn(a, b);
    hi = *(uint32_t*)&h2;
    float la = a - __bfloat162float(h2.x);
    float lb = b - __bfloat162float(h2.y);
    __nv_bfloat162 l2 = __floats2bfloat162_rn(la, lb);
    lo = *(uint32_t*)&l2;
}
// fast exp2 on the FMA pipe (|err| ~3e-6), input <= 0
__device__ __forceinline__ float exp2p(float x) {
    x = fmaxf(x, -80.f);
    float r = rintf(x);
    float f = x - r;
    float p = 1.33335581e-3f;
    p = fmaf(p, f, 9.61812910e-3f);
    p = fmaf(p, f, 5.55041087e-2f);
    p = fmaf(p, f, 2.40226507e-1f);
    p = fmaf(p, f, 6.93147180e-1f);
    p = fmaf(p, f, 1.0f);
    return p * __int_as_float(((int)r + 127) << 23);
}

// ---------------------------------------------------------------------------
// Scratch (device globals)
// ---------------------------------------------------------------------------
__device__ __nv_bfloat16 g_ah[NTOK * D_];        // nx hi
__device__ __nv_bfloat16 g_al[NTOK * D_];        // nx lo
__device__ __nv_bfloat16 g_wth[NQKV * D_];       // [wq|wk|wv]^T hi  [7680,5120]
__device__ __nv_bfloat16 g_wtl[NQKV * D_];
__device__ __nv_bfloat16 g_woh[D_ * D_];         // wo^T hi [5120,5120]
__device__ __nv_bfloat16 g_wol[D_ * D_];
__device__ float g_qkv[NTOK * NQKV];             // fused qkv output (fp32)
__device__ __nv_bfloat16 g_qh[NTOK * HQ_ * HD_]; // q head-major [B,HQ,T,HD]
__device__ __nv_bfloat16 g_ql[NTOK * HQ_ * HD_];
__device__ __nv_bfloat16 g_kh[NTOK * HK_ * HD_]; // k head-major [B,HK,T,HD]
__device__ __nv_bfloat16 g_kl[NTOK * HK_ * HD_];
__device__ __nv_bfloat16 g_vh[NTOK * HK_ * HD_];
__device__ __nv_bfloat16 g_vl[NTOK * HK_ * HD_];
__device__ __nv_bfloat16 g_oh[NTOK * D_];        // attn out hi [tok, D]
__device__ __nv_bfloat16 g_ol[NTOK * D_];
__device__ float g_cos[T_ * RD_];
__device__ float g_sin[T_ * RD_];

// ---------------------------------------------------------------------------
// Kernel 0: RoPE tables (fp64)
// ---------------------------------------------------------------------------
__global__ void rope_table_kernel(float* __restrict__ tc, float* __restrict__ ts) {
    int idx = blockIdx.x * 256 + threadIdx.x;
    if (idx >= T_ * RD_) return;
    int t = idx / RD_;
    int i = idx % RD_;
    int f = i % 20;
    double invf = pow(5000000.0, -(double)f / 20.0);
    double ang = (double)t * invf;
    tc[idx] = (float)cos(ang);
    ts[idx] = (float)sin(ang);
}

// ---------------------------------------------------------------------------
// Kernel 1: weight transpose + bf16 split
// ---------------------------------------------------------------------------
__global__ __launch_bounds__(256) void wsplit_t(
    const float* __restrict__ src, __nv_bfloat16* __restrict__ dh,
    __nv_bfloat16* __restrict__ dl, int N, int Kdim, int n0) {
    __shared__ float tile[32][33];
    int kb = blockIdx.y * 32, nb = blockIdx.x * 32;
    int tx = threadIdx.x & 31, ty = threadIdx.x >> 5;
    #pragma unroll
    for (int i = 0; i < 4; i++)
        tile[ty + i * 8][tx] = src[(size_t)(kb + ty + i * 8) * N + nb + tx];
    __syncthreads();
    #pragma unroll
    for (int i = 0; i < 4; i++) {
        int r = ty + i * 8;
        float v = tile[tx][r];
        __nv_bfloat16 h, l;
        split2(v, h, l);
        size_t o = (size_t)(n0 + nb + r) * Kdim + kb + tx;
        dh[o] = h; dl[o] = l;
    }
}

// ---------------------------------------------------------------------------
// Kernel 2: RMS layernorm -> bf16 hi/lo
// ---------------------------------------------------------------------------
__global__ __launch_bounds__(256) void rmsnorm_kernel(
    const float* __restrict__ x, const float* __restrict__ w,
    const float* __restrict__ b, __nv_bfloat16* __restrict__ oh,
    __nv_bfloat16* __restrict__ ol) {
    int row = blockIdx.x;
    const float4* xr = (const float4*)(x + (size_t)row * D_);
    float ss = 0.f;
    #pragma unroll
    for (int i = threadIdx.x; i < D_ / 4; i += 256) {
        float4 v = xr[i];
        ss += v.x * v.x + v.y * v.y + v.z * v.z + v.w * v.w;
    }
    #pragma unroll
    for (int m = 16; m; m >>= 1) ss += __shfl_xor_sync(0xffffffffu, ss, m);
    __shared__ float red[8];
    if ((threadIdx.x & 31) == 0) red[threadIdx.x >> 5] = ss;
    __syncthreads();
    float tot = 0.f;
    #pragma unroll
    for (int i = 0; i < 8; i++) tot += red[i];
    float r = rsqrtf(tot * (1.0f / (float)D_) + EPS_);

    const float4* w4 = (const float4*)w;
    const float4* b4 = (const float4*)b;
    for (int i = threadIdx.x; i < D_ / 4; i += 256) {
        float4 v = xr[i], ww = w4[i], bb = b4[i];
        float o0 = v.x * r * ww.x + bb.x;
        float o1 = v.y * r * ww.y + bb.y;
        float o2 = v.z * r * ww.z + bb.z;
        float o3 = v.w * r * ww.w + bb.w;
        uint32_t h01, l01, h23, l23;
        packhl(o0, o1, h01, l01);
        packhl(o2, o3, h23, l23);
        size_t base = (size_t)row * D_ + i * 4;
        *(uint32_t*)(oh + base)     = h01;
        *(uint32_t*)(oh + base + 2) = h23;
        *(uint32_t*)(ol + base)     = l01;
        *(uint32_t*)(ol + base + 2) = l23;
    }
}

// ---------------------------------------------------------------------------
// Kernel 3: HMMA GEMM (unchanged from R3)
// ---------------------------------------------------------------------------
#define BM 128
#define BN 256
#define BK 32
#define PAD 40
#define ATILE (BM * PAD * 2)
#define BTILE (BN * PAD * 2)
#define BUFSZ (2 * ATILE + 2 * BTILE)
#define GEMM_SMEM (2 * BUFSZ)

__global__ __launch_bounds__(512, 1) void hmma_gemm(
    const __nv_bfloat16* __restrict__ Ah, const __nv_bfloat16* __restrict__ Al,
    const __nv_bfloat16* __restrict__ Bh, const __nv_bfloat16* __restrict__ Bl,
    float* __restrict__ C, int Kdim, int Nstride) {
    extern __shared__ char sm[];
    uint32_t smb = smem_u32(sm);
    const int tid = threadIdx.x;
    const int lane = tid & 31, wid = tid >> 5;
    const int wm = (wid >> 3) * 64;
    const int wn = (wid & 7) * 32;

    const size_t mBase = (size_t)blockIdx.y * BM;
    const size_t nBase = (size_t)blockIdx.x * BN;
    const __nv_bfloat16* Ag[2] = {Ah + mBase * Kdim, Al + mBase * Kdim};
    const __nv_bfloat16* Bg[2] = {Bh + nBase * Kdim, Bl + nBase * Kdim};

    auto load_tiles = [&](int buf, int kc) {
        uint32_t base = smb + buf * BUFSZ;
        #pragma unroll
        for (int j = 0; j < 6; j++) {
            int c = tid + j * 512;
            const __nv_bfloat16* src;
            uint32_t soff;
            int cc;
            if (c < 1024) {
                int hl = c >> 9; cc = c & 511;
                src = Ag[hl]; soff = base + hl * ATILE;
            } else {
                int c2 = c - 1024;
                int hl = c2 >> 10; cc = c2 & 1023;
                src = Bg[hl]; soff = base + 2 * ATILE + hl * BTILE;
            }
            int row = cc >> 2, col = (cc & 3) << 3;
            cp16(soff + (row * PAD + col) * 2,
                 src + (size_t)row * Kdim + kc + col);
        }
    };

    float acc[4][4][4];
    #pragma unroll
    for (int i = 0; i < 4; i++)
        #pragma unroll
        for (int j = 0; j < 4; j++)
            #pragma unroll
            for (int e = 0; e < 4; e++) acc[i][j][e] = 0.f;

    const int t8 = lane >> 3, r8 = lane & 7;
    const int aRow = wm + r8 + ((t8 & 1) << 3);
    const int aCol = (t8 >> 1) << 3;
    const int bRow = wn + r8 + ((t8 >> 1) << 3);
    const int bCol = (t8 & 1) << 3;

    const int KITERS = Kdim / BK;
    load_tiles(0, 0);
    CP_COMMIT();

    for (int it = 0; it < KITERS; ++it) {
        if (it + 1 < KITERS) {
            load_tiles((it + 1) & 1, (it + 1) * BK);
            CP_COMMIT();
            CP_WAIT1();
        } else {
            CP_WAIT0();
        }
        __syncthreads();

        uint32_t base = smb + (it & 1) * BUFSZ;
        uint32_t sAh = base, sAl = base + ATILE;
        uint32_t sBh = base + 2 * ATILE, sBl = sBh + BTILE;

        #pragma unroll
        for (int ks = 0; ks < 2; ks++) {
            int k0 = ks << 4;
            uint32_t ah[4][4];
            #pragma unroll
            for (int mf = 0; mf < 4; mf++)
                ldm4(ah[mf], sAh + ((aRow + mf * 16) * PAD + k0 + aCol) * 2);
            uint32_t bh[4][2];
            #pragma unroll
            for (int nf2 = 0; nf2 < 2; nf2++) {
                uint32_t r[4];
                ldm4(r, sBh + ((bRow + nf2 * 16) * PAD + k0 + bCol) * 2);
                bh[nf2 * 2][0] = r[0]; bh[nf2 * 2][1] = r[1];
                bh[nf2 * 2 + 1][0] = r[2]; bh[nf2 * 2 + 1][1] = r[3];
            }
            #pragma unroll
            for (int mf = 0; mf < 4; mf++)
                #pragma unroll
                for (int nf = 0; nf < 4; nf++)
                    mma_bf16(acc[mf][nf], ah[mf], bh[nf]);

            uint32_t bl[4][2];
            #pragma unroll
            for (int nf2 = 0; nf2 < 2; nf2++) {
                uint32_t r[4];
                ldm4(r, sBl + ((bRow + nf2 * 16) * PAD + k0 + bCol) * 2);
                bl[nf2 * 2][0] = r[0]; bl[nf2 * 2][1] = r[1];
                bl[nf2 * 2 + 1][0] = r[2]; bl[nf2 * 2 + 1][1] = r[3];
            }
            #pragma unroll
            for (int mf = 0; mf < 4; mf++)
                #pragma unroll
                for (int nf = 0; nf < 4; nf++)
                    mma_bf16(acc[mf][nf], ah[mf], bl[nf]);

            uint32_t al[4][4];
            #pragma unroll
            for (int mf = 0; mf < 4; mf++)
                ldm4(al[mf], sAl + ((aRow + mf * 16) * PAD + k0 + aCol) * 2);
            #pragma unroll
            for (int mf = 0; mf < 4; mf++)
                #pragma unroll
                for (int nf = 0; nf < 4; nf++)
                    mma_bf16(acc[mf][nf], al[mf], bh[nf]);
        }
        __syncthreads();
    }

    float* Cb = C + (mBase + wm) * Nstride + nBase + wn;
    const int er = lane >> 2, ec = (lane & 3) * 2;
    #pragma unroll
    for (int mf = 0; mf < 4; mf++) {
        #pragma unroll
        for (int nf = 0; nf < 4; nf++) {
            float* p0 = Cb + (size_t)(mf * 16 + er) * Nstride + nf * 8 + ec;
            p0[0] = acc[mf][nf][0];
            p0[1] = acc[mf][nf][1];
            float* p1 = p0 + 8 * (size_t)Nstride;
            p1[0] = acc[mf][nf][2];
            p1[1] = acc[mf][nf][3];
        }
    }
}

// ---------------------------------------------------------------------------
// Kernel 4: head prep: optional per-head RMS + partial RoPE, bf16 hi/lo split,
// layout transform [tok][h][HD] -> [b][h][t][HD]. One warp per row.
// ---------------------------------------------------------------------------
__global__ __launch_bounds__(256) void head_prep(
    const float* __restrict__ src_base, int H, int src_off,
    const float* __restrict__ w, const float* __restrict__ tcos,
    const float* __restrict__ tsin, int do_norm,
    __nv_bfloat16* __restrict__ dh, __nv_bfloat16* __restrict__ dl) {
    int rowi = blockIdx.x * 8 + (threadIdx.x >> 5);
    int lane = threadIdx.x & 31;
    int h = rowi % H;
    int tok = rowi / H;
    int t = tok & (T_ - 1);
    int b = tok >> 11;

    const float* p = src_base + (size_t)tok * NQKV + src_off + h * HD_;
    float v[5];
    #pragma unroll
    for (int i = 0; i < 5; i++) v[i] = p[lane + 32 * i];

    if (do_norm) {
        float ss = 0.f;
        #pragma unroll
        for (int i = 0; i < 5; i++) ss += v[i] * v[i];
        #pragma unroll
        for (int m = 16; m; m >>= 1) ss += __shfl_xor_sync(0xffffffffu, ss, m);
        float r = rsqrtf(ss * (1.0f / (float)HD_) + EPS_);
        const float* wh = w + h * HD_;
        #pragma unroll
        for (int i = 0; i < 5; i++) v[i] *= r * wh[lane + 32 * i];
        {   // RoPE d = lane (0..31)
            float partner = __shfl_xor_sync(0xffffffffu, v[0], 1);
            float rot = (lane & 1) ? partner : -partner;
            v[0] = v[0] * tcos[t * RD_ + lane] + rot * tsin[t * RD_ + lane];
        }
        {   // RoPE d = 32..39
            float partner = __shfl_xor_sync(0xffffffffu, v[1], 1);
            if (lane < 8) {
                int d = 32 + lane;
                float rot = (lane & 1) ? partner : -partner;
                v[1] = v[1] * tcos[t * RD_ + d] + rot * tsin[t * RD_ + d];
            }
        }
    }
    size_t dbase = ((size_t)(b * H + h) * T_ + t) * HD_;
    #pragma unroll
    for (int i = 0; i < 5; i++) {
        __nv_bfloat16 hh, ll;
        split2(v[i], hh, ll);
        dh[dbase + lane + 32 * i] = hh;
        dl[dbase + lane + 32 * i] = ll;
    }
}

// ---------------------------------------------------------------------------
// Kernel 5: HMMA causal flash attention. BQ=128, BKV=64, 256 threads (8 warps).
// Q/K/V bf16 hi/lo in smem (pad stride 168 elems = 21 x 16B, conflict-free).
// K double-buffered, V single-buffered (cp.async group choreography).
// ---------------------------------------------------------------------------
#define PADF 168
#define ROWB 336                    // PADF * 2 bytes
#define FQ_SZ 43008                 // 128 * ROWB
#define FK_SZ 21504                 // 64 * ROWB
#define FKBUF 86016                 // Qh + Ql
#define FVOFF 172032                // Qh+Ql + 2 K bufs (hi+lo each)
#define FLASH_SMEM 215040

__global__ __launch_bounds__(256, 1) void flash_hmma(
    const __nv_bfloat16* __restrict__ Qh_, const __nv_bfloat16* __restrict__ Ql_,
    const __nv_bfloat16* __restrict__ Kh_, const __nv_bfloat16* __restrict__ Kl_,
    const __nv_bfloat16* __restrict__ Vh_, const __nv_bfloat16* __restrict__ Vl_,
    __nv_bfloat16* __restrict__ Oh, __nv_bfloat16* __restrict__ Ol) {
    extern __shared__ char sm[];
    uint32_t smb = smem_u32(sm);
    const int qt = (T_ / 128 - 1) - blockIdx.x;   // heavy tiles first
    const int h = blockIdx.y, b = blockIdx.z;
    const int hk = h >> 2;
    const int tid = threadIdx.x, lane = tid & 31, wid = tid >> 5;

    const __nv_bfloat16* Qgh = Qh_ + ((size_t)(b * HQ_ + h) * T_ + qt * 128) * HD_;
    const __nv_bfloat16* Qgl = Ql_ + ((size_t)(b * HQ_ + h) * T_ + qt * 128) * HD_;
    const __nv_bfloat16* Kgh = Kh_ + (size_t)(b * HK_ + hk) * T_ * HD_;
    const __nv_bfloat16* Kgl = Kl_ + (size_t)(b * HK_ + hk) * T_ * HD_;
    const __nv_bfloat16* Vgh = Vh_ + (size_t)(b * HK_ + hk) * T_ * HD_;
    const __nv_bfloat16* Vgl = Vl_ + (size_t)(b * HK_ + hk) * T_ * HD_;

    // Q tile: 128x160 hi + lo, 5120 x 16B chunks
    #pragma unroll
    for (int j = 0; j < 20; j++) {
        int c = tid + j * 256;
        int hl = c >= 2560;
        int cc = c - hl * 2560;
        int row = cc / 20, col = (cc % 20) * 8;
        cp16(smb + hl * FQ_SZ + row * ROWB + col * 2,
             (hl ? Qgl : Qgh) + row * HD_ + col);
    }
    auto load_k = [&](int buf, int kt) {
        uint32_t base = smb + FKBUF + buf * (2 * FK_SZ);
        const __nv_bfloat16* s0 = Kgh + (size_t)kt * 64 * HD_;
        const __nv_bfloat16* s1 = Kgl + (size_t)kt * 64 * HD_;
        #pragma unroll
        for (int j = 0; j < 10; j++) {
            int c = tid + j * 256;
            int hl = c >= 1280;
            int cc = c - hl * 1280;
            int row = cc / 20, col = (cc % 20) * 8;
            cp16(base + hl * FK_SZ + row * ROWB + col * 2,
                 (hl ? s1 : s0) + row * HD_ + col);
        }
    };
    auto load_v = [&](int kt) {
        uint32_t base = smb + FVOFF;
        const __nv_bfloat16* s0 = Vgh + (size_t)kt * 64 * HD_;
        const __nv_bfloat16* s1 = Vgl + (size_t)kt * 64 * HD_;
        #pragma unroll
        for (int j = 0; j < 10; j++) {
            int c = tid + j * 256;
            int hl = c >= 1280;
            int cc = c - hl * 1280;
            int row = cc / 20, col = (cc % 20) * 8;
            cp16(base + hl * FK_SZ + row * ROWB + col * 2,
                 (hl ? s1 : s0) + row * HD_ + col);
        }
    };

    load_k(0, 0);
    CP_COMMIT();                 // group: Q + K0
    load_v(0);
    CP_COMMIT();                 // group: V0

    float m0 = -1e30f, m1 = -1e30f, l0 = 0.f, l1 = 0.f;
    float o[20][4];
    #pragma unroll
    for (int f = 0; f < 20; f++)
        #pragma unroll
        for (int e = 0; e < 4; e++) o[f][e] = 0.f;

    const int gr = lane >> 2, ct = lane & 3;
    const int ldrow = (lane & 7) + ((lane >> 3) & 1) * 8;
    const int ldcol = ((lane >> 4) & 1) * 8;
    const uint32_t qh_b = smb + (wid * 16 + ldrow) * ROWB + ldcol * 2;
    const uint32_t ql_b = qh_b + FQ_SZ;
    const int rowg0 = qt * 128 + wid * 16 + gr;

    const int nkt = 2 * qt + 2;
    const float sc = 0.07905694150420949f * 1.4426950408889634f;  // scale*log2e

    for (int kt = 0; kt < nkt; kt++) {
        CP_WAIT1();               // K(kt) ready (V(kt) may still be in flight)
        __syncthreads();
        if (kt + 1 < nkt) { load_k((kt + 1) & 1, kt + 1); CP_COMMIT(); }

        // ---- S = Q K^T (hi/lo x3) ----
        float s[8][4];
        #pragma unroll
        for (int f = 0; f < 8; f++)
            #pragma unroll
            for (int e = 0; e < 4; e++) s[f][e] = 0.f;

        uint32_t kb = smb + FKBUF + (kt & 1) * (2 * FK_SZ) + ldrow * ROWB + ldcol * 2;
        #pragma unroll
        for (int ks = 0; ks < 10; ks++) {
            uint32_t ah[4], al[4];
            ldm4(ah, qh_b + ks * 32);
            ldm4(al, ql_b + ks * 32);
            #pragma unroll
            for (int ng = 0; ng < 4; ng++) {
                uint32_t rh[4], rl[4];
                ldm4(rh, kb + ng * 16 * ROWB + ks * 32);
                ldm4(rl, kb + FK_SZ + ng * 16 * ROWB + ks * 32);
                uint32_t bh0[2] = {rh[0], rh[2]}, bh1[2] = {rh[1], rh[3]};
                uint32_t bl0[2] = {rl[0], rl[2]}, bl1[2] = {rl[1], rl[3]};
                mma_bf16(s[2 * ng], ah, bh0);
                mma_bf16(s[2 * ng], ah, bl0);
                mma_bf16(s[2 * ng], al, bh0);
                mma_bf16(s[2 * ng + 1], ah, bh1);
                mma_bf16(s[2 * ng + 1], ah, bl1);
                mma_bf16(s[2 * ng + 1], al, bh1);
            }
        }

        // ---- mask + scale (base-2 domain) ----
        if (kt * 64 + 63 > qt * 128 + wid * 16) {
            #pragma unroll
            for (int f = 0; f < 8; f++) {
                int col = kt * 64 + f * 8 + 2 * ct;
                s[f][0] = (col     > rowg0)     ? -1e30f : s[f][0] * sc;
                s[f][1] = (col + 1 > rowg0)     ? -1e30f : s[f][1] * sc;
                s[f][2] = (col     > rowg0 + 8) ? -1e30f : s[f][2] * sc;
                s[f][3] = (col + 1 > rowg0 + 8) ? -1e30f : s[f][3] * sc;
            }
        } else {
            #pragma unroll
            for (int f = 0; f < 8; f++)
                #pragma unroll
                for (int e = 0; e < 4; e++) s[f][e] *= sc;
        }

        // ---- online softmax (exp2 on FMA pipe) ----
        float r0 = -1e30f, r1 = -1e30f;
        #pragma unroll
        for (int f = 0; f < 8; f++) {
            r0 = fmaxf(r0, fmaxf(s[f][0], s[f][1]));
            r1 = fmaxf(r1, fmaxf(s[f][2], s[f][3]));
        }
        r0 = fmaxf(r0, __shfl_xor_sync(0xffffffffu, r0, 1));
        r0 = fmaxf(r0, __shfl_xor_sync(0xffffffffu, r0, 2));
        r1 = fmaxf(r1, __shfl_xor_sync(0xffffffffu, r1, 1));
        r1 = fmaxf(r1, __shfl_xor_sync(0xffffffffu, r1, 2));
        float mn0 = fmaxf(m0, r0), mn1 = fmaxf(m1, r1);
        float a0 = exp2p(m0 - mn0), a1 = exp2p(m1 - mn1);
        m0 = mn0; m1 = mn1;

        float rs0 = 0.f, rs1 = 0.f;
        uint32_t pA[8], pB[8], qA[8], qB[8];
        #pragma unroll
        for (int f = 0; f < 8; f++) {
            float p0 = exp2p(s[f][0] - mn0);
            float p1 = exp2p(s[f][1] - mn0);
            float p2 = exp2p(s[f][2] - mn1);
            float p3 = exp2p(s[f][3] - mn1);
            rs0 += p0 + p1; rs1 += p2 + p3;
            packhl(p0, p1, pA[f], qA[f]);
            packhl(p2, p3, pB[f], qB[f]);
        }
        rs0 += __shfl_xor_sync(0xffffffffu, rs0, 1);
        rs0 += __shfl_xor_sync(0xffffffffu, rs0, 2);
        rs1 += __shfl_xor_sync(0xffffffffu, rs1, 1);
        rs1 += __shfl_xor_sync(0xffffffffu, rs1, 2);
        l0 = l0 * a0 + rs0;
        l1 = l1 * a1 + rs1;
        #pragma unroll
        for (int f = 0; f < 20; f++) {
            o[f][0] *= a0; o[f][1] *= a0; o[f][2] *= a1; o[f][3] *= a1;
        }

        // ---- wait for V, then O += P V ----
        if (kt + 1 < nkt) { CP_WAIT1(); } else { CP_WAIT0(); }
        __syncthreads();

        #pragma unroll
        for (int ks = 0; ks < 4; ks++) {
            uint32_t a_h[4] = {pA[2 * ks], pB[2 * ks], pA[2 * ks + 1], pB[2 * ks + 1]};
            uint32_t a_l[4] = {qA[2 * ks], qB[2 * ks], qA[2 * ks + 1], qB[2 * ks + 1]};
            uint32_t vb = smb + FVOFF + (ks * 16 + ldrow) * ROWB + ldcol * 2;
            #pragma unroll
            for (int nb = 0; nb < 10; nb++) {
                uint32_t rh[4], rl[4];
                ldm4t(rh, vb + nb * 32);
                ldm4t(rl, vb + FK_SZ + nb * 32);
                uint32_t bh0[2] = {rh[0], rh[1]}, bh1[2] = {rh[2], rh[3]};
                uint32_t bl0[2] = {rl[0], rl[1]}, bl1[2] = {rl[2], rl[3]};
                mma_bf16(o[2 * nb], a_h, bh0);
                mma_bf16(o[2 * nb], a_h, bl0);
                mma_bf16(o[2 * nb], a_l, bh0);
                mma_bf16(o[2 * nb + 1], a_h, bh1);
                mma_bf16(o[2 * nb + 1], a_h, bl1);
                mma_bf16(o[2 * nb + 1], a_l, bh1);
            }
        }
        __syncthreads();          // V consumed
        if (kt + 1 < nkt) { load_v(kt + 1); CP_COMMIT(); }
    }

    // ---- epilogue: normalize, split to bf16 hi/lo, write [tok][D] ----
    float i0 = 1.f / l0, i1 = 1.f / l1;
    size_t rb0 = (size_t)(b * T_ + qt * 128 + wid * 16 + gr) * D_ + h * HD_;
    size_t rb1 = rb0 + 8 * (size_t)D_;
    #pragma unroll
    for (int f = 0; f < 20; f++) {
        int col = f * 8 + 2 * ct;
        uint32_t h01, l01, h23, l23;
        packhl(o[f][0] * i0, o[f][1] * i0, h01, l01);
        packhl(o[f][2] * i1, o[f][3] * i1, h23, l23);
        *(uint32_t*)(Oh + rb0 + col) = h01;
        *(uint32_t*)(Ol + rb0 + col) = l01;
        *(uint32_t*)(Oh + rb1 + col) = h23;
        *(uint32_t*)(Ol + rb1 + col) = l23;
    }
}

// ---------------------------------------------------------------------------
// Host launch
// ---------------------------------------------------------------------------
extern "C" void kernel_launch(void* const* d_in, const int* in_sizes, int n_in,
                              void* d_out, int out_size) {
    const float* x      = (const float*)d_in[0];
    const float* wq     = (const float*)d_in[1];
    const float* wk     = (const float*)d_in[2];
    const float* wv     = (const float*)d_in[3];
    const float* wo     = (const float*)d_in[4];
    const float* norm_w = (const float*)d_in[5];
    const float* norm_b = (const float*)d_in[6];
    const float* qn_w   = (const float*)d_in[7];
    const float* kn_w   = (const float*)d_in[8];
    float* out = (float*)d_out;

    __nv_bfloat16 *ah, *al, *wth, *wtl, *woh, *wol, *oh, *ol;
    __nv_bfloat16 *qh, *ql, *kh, *kl, *vh, *vl;
    float *qkv, *tcos, *tsin;
    cudaGetSymbolAddress((void**)&ah,   g_ah);
    cudaGetSymbolAddress((void**)&al,   g_al);
    cudaGetSymbolAddress((void**)&wth,  g_wth);
    cudaGetSymbolAddress((void**)&wtl,  g_wtl);
    cudaGetSymbolAddress((void**)&woh,  g_woh);
    cudaGetSymbolAddress((void**)&wol,  g_wol);
    cudaGetSymbolAddress((void**)&oh,   g_oh);
    cudaGetSymbolAddress((void**)&ol,   g_ol);
    cudaGetSymbolAddress((void**)&qh,   g_qh);
    cudaGetSymbolAddress((void**)&ql,   g_ql);
    cudaGetSymbolAddress((void**)&kh,   g_kh);
    cudaGetSymbolAddress((void**)&kl,   g_kl);
    cudaGetSymbolAddress((void**)&vh,   g_vh);
    cudaGetSymbolAddress((void**)&vl,   g_vl);
    cudaGetSymbolAddress((void**)&qkv,  g_qkv);
    cudaGetSymbolAddress((void**)&tcos, g_cos);
    cudaGetSymbolAddress((void**)&tsin, g_sin);

    cudaFuncSetAttribute(hmma_gemm, cudaFuncAttributeMaxDynamicSharedMemorySize, GEMM_SMEM);
    cudaFuncSetAttribute(flash_hmma, cudaFuncAttributeMaxDynamicSharedMemorySize, FLASH_SMEM);

    // 0. rope tables
    rope_table_kernel<<<(T_ * RD_ + 255) / 256, 256>>>(tcos, tsin);
    // 1. weight transpose + split
    wsplit_t<<<dim3(D_ / 32, D_ / 32), 256>>>(wq, wth, wtl, D_, D_, 0);
    wsplit_t<<<dim3((HK_ * HD_) / 32, D_ / 32), 256>>>(wk, wth, wtl, HK_ * HD_, D_, KOFF);
    wsplit_t<<<dim3((HK_ * HD_) / 32, D_ / 32), 256>>>(wv, wth, wtl, HK_ * HD_, D_, VOFF);
    wsplit_t<<<dim3(D_ / 32, D_ / 32), 256>>>(wo, woh, wol, D_, D_, 0);
    // 2. RMS layernorm -> bf16 hi/lo
    rmsnorm_kernel<<<NTOK, 256>>>(x, norm_w, norm_b, ah, al);
    // 3. fused QKV projection (HMMA bf16 x3)
    hmma_gemm<<<dim3(NQKV / BN, NTOK / BM), 512, GEMM_SMEM>>>(
        ah, al, wth, wtl, qkv, D_, NQKV);
    // 4. head prep: q norm+rope, k norm+rope, v split; layout [b][h][t][hd]
    head_prep<<<(NTOK * HQ_) / 8, 256>>>(qkv, HQ_, 0,    qn_w, tcos, tsin, 1, qh, ql);
    head_prep<<<(NTOK * HK_) / 8, 256>>>(qkv, HK_, KOFF, kn_w, tcos, tsin, 1, kh, kl);
    head_prep<<<(NTOK * HK_) / 8, 256>>>(qkv, HK_, VOFF, kn_w, tcos, tsin, 0, vh, vl);
    // 5. HMMA flash attention
    flash_hmma<<<dim3(T_ / 128, HQ_, B_), 256, FLASH_SMEM>>>(
        qh, ql, kh, kl, vh, vl, oh, ol);
    // 6. output projection (HMMA bf16 x3)
    hmma_gemm<<<dim3(D_ / BN, NTOK / BM), 512, GEMM_SMEM>>>(
        oh, ol, woh, wol, out, D_, D_);
}

// round 5
// speedup vs baseline: 6.5179x; 2.1352x over previous
#include <cuda_runtime.h>
#include <cuda_bf16.h>
#include <cuda_fp16.h>
#include <math.h>
#include <cstdint>

// Problem constants
#define B_  2
#define T_  2048
#define D_  5120
#define HQ_ 32
#define HK_ 8
#define HD_ 160
#define RD_ 40
#define NTOK (B_ * T_)          // 4096
#define EPS_ 1e-5f
#define NQKV 7680               // 5120 + 1280 + 1280
#define KOFF 5120
#define VOFF 6400

// ---------------------------------------------------------------------------
// PTX helpers (generic sm_80+ subset)
// ---------------------------------------------------------------------------
__device__ __forceinline__ uint32_t smem_u32(const void* p) {
    uint32_t a;
    asm("{ .reg .u64 t; cvta.to.shared.u64 t, %1; cvt.u32.u64 %0, t; }" : "=r"(a) : "l"(p));
    return a;
}
__device__ __forceinline__ void cp16(uint32_t s, const void* g) {
    asm volatile("cp.async.cg.shared.global [%0], [%1], 16;" :: "r"(s), "l"(g));
}
#define CP_COMMIT() asm volatile("cp.async.commit_group;")
#define CP_WAIT0()  asm volatile("cp.async.wait_group 0;")
#define CP_WAIT1()  asm volatile("cp.async.wait_group 1;")
#define CP_WAIT2()  asm volatile("cp.async.wait_group 2;")

__device__ __forceinline__ void ldm4(uint32_t* r, uint32_t addr) {
    asm volatile("ldmatrix.sync.aligned.m8n8.x4.shared.b16 {%0,%1,%2,%3}, [%4];"
                 : "=r"(r[0]), "=r"(r[1]), "=r"(r[2]), "=r"(r[3]) : "r"(addr));
}
__device__ __forceinline__ void ldm4t(uint32_t* r, uint32_t addr) {
    asm volatile("ldmatrix.sync.aligned.m8n8.x4.trans.shared.b16 {%0,%1,%2,%3}, [%4];"
                 : "=r"(r[0]), "=r"(r[1]), "=r"(r[2]), "=r"(r[3]) : "r"(addr));
}
__device__ __forceinline__ void mma_bf16(float* c, const uint32_t* a, const uint32_t* b) {
    asm volatile(
        "mma.sync.aligned.m16n8k16.row.col.f32.bf16.bf16.f32 "
        "{%0,%1,%2,%3}, {%4,%5,%6,%7}, {%8,%9}, {%0,%1,%2,%3};"
        : "+f"(c[0]), "+f"(c[1]), "+f"(c[2]), "+f"(c[3])
        : "r"(a[0]), "r"(a[1]), "r"(a[2]), "r"(a[3]), "r"(b[0]), "r"(b[1]));
}
__device__ __forceinline__ void mma_f16(float* c, const uint32_t* a, const uint32_t* b) {
    asm volatile(
        "mma.sync.aligned.m16n8k16.row.col.f32.f16.f16.f32 "
        "{%0,%1,%2,%3}, {%4,%5,%6,%7}, {%8,%9}, {%0,%1,%2,%3};"
        : "+f"(c[0]), "+f"(c[1]), "+f"(c[2]), "+f"(c[3])
        : "r"(a[0]), "r"(a[1]), "r"(a[2]), "r"(a[3]), "r"(b[0]), "r"(b[1]));
}

__device__ __forceinline__ void split2(float v, __nv_bfloat16& h, __nv_bfloat16& l) {
    h = __float2bfloat16(v);
    l = __float2bfloat16(v - __bfloat162float(h));
}
// pack pair of floats -> bf16x2 hi frag and lo frag
__device__ __forceinline__ void packhl(float a, float b, uint32_t& hi, uint32_t& lo) {
    __nv_bfloat162 h2 = __floats2bfloat162_rn(a, b);
    hi = *(uint32_t*)&h2;
    float la = a - __bfloat162float(h2.x);
    float lb = b - __bfloat162float(h2.y);
    __nv_bfloat162 l2 = __floats2bfloat162_rn(la, lb);
    lo = *(uint32_t*)&l2;
}
// fast exp2 on the FMA pipe (|err| ~3e-6), input <= 0
__device__ __forceinline__ float exp2p(float x) {
    x = fmaxf(x, -80.f);
    float r = rintf(x);
    float f = x - r;
    float p = 1.33335581e-3f;
    p = fmaf(p, f, 9.61812910e-3f);
    p = fmaf(p, f, 5.55041087e-2f);
    p = fmaf(p, f, 2.40226507e-1f);
    p = fmaf(p, f, 6.93147180e-1f);
    p = fmaf(p, f, 1.0f);
    return p * __int_as_float(((int)r + 127) << 23);
}

// ---------------------------------------------------------------------------
// Scratch (device globals)
// ---------------------------------------------------------------------------
__device__ __half g_af[NTOK * D_];               // nx fp16
__device__ __half g_wtf[NQKV * D_];              // [wq|wk|wv]^T fp16 [7680,5120]
__device__ __half g_wof[D_ * D_];                // wo^T fp16 [5120,5120]
__device__ float  g_qkv[NTOK * NQKV];            // fused qkv output (fp32)
__device__ __nv_bfloat16 g_qh[NTOK * HQ_ * HD_]; // q head-major [B,HQ,T,HD]
__device__ __nv_bfloat16 g_ql[NTOK * HQ_ * HD_];
__device__ __nv_bfloat16 g_kh[NTOK * HK_ * HD_];
__device__ __nv_bfloat16 g_kl[NTOK * HK_ * HD_];
__device__ __nv_bfloat16 g_vh[NTOK * HK_ * HD_];
__device__ __nv_bfloat16 g_vl[NTOK * HK_ * HD_];
__device__ __half g_of[NTOK * D_];               // attn out fp16 [tok, D]
__device__ float g_cos[T_ * RD_];
__device__ float g_sin[T_ * RD_];

// ---------------------------------------------------------------------------
// Kernel 0: RoPE tables (fp64)
// ---------------------------------------------------------------------------
__global__ void rope_table_kernel(float* __restrict__ tc, float* __restrict__ ts) {
    int idx = blockIdx.x * 256 + threadIdx.x;
    if (idx >= T_ * RD_) return;
    int t = idx / RD_;
    int i = idx % RD_;
    int f = i % 20;
    double invf = pow(5000000.0, -(double)f / 20.0);
    double ang = (double)t * invf;
    tc[idx] = (float)cos(ang);
    ts[idx] = (float)sin(ang);
}

// ---------------------------------------------------------------------------
// Kernel 1: weight transpose -> fp16, 3 sources fused (wq|wk|wv column blocks)
// For wo pass the same ptr in all three slots (all nb < 5120).
// ---------------------------------------------------------------------------
__global__ __launch_bounds__(256) void wsplit_h(
    const float* __restrict__ w0, const float* __restrict__ w1,
    const float* __restrict__ w2, __half* __restrict__ dst) {
    __shared__ float tile[32][33];
    int kb = blockIdx.y * 32, nb = blockIdx.x * 32;
    const float* src; int N; int nloc;
    if (nb < KOFF)      { src = w0; N = D_;        nloc = nb; }
    else if (nb < VOFF) { src = w1; N = HK_ * HD_; nloc = nb - KOFF; }
    else                { src = w2; N = HK_ * HD_; nloc = nb - VOFF; }
    int tx = threadIdx.x & 31, ty = threadIdx.x >> 5;
    #pragma unroll
    for (int i = 0; i < 4; i++)
        tile[ty + i * 8][tx] = src[(size_t)(kb + ty + i * 8) * N + nloc + tx];
    __syncthreads();
    #pragma unroll
    for (int i = 0; i < 4; i++) {
        int r = ty + i * 8;
        dst[(size_t)(nb + r) * D_ + kb + tx] = __float2half_rn(tile[tx][r]);
    }
}

// ---------------------------------------------------------------------------
// Kernel 2: RMS layernorm -> fp16
// ---------------------------------------------------------------------------
__global__ __launch_bounds__(256) void rmsnorm_kernel(
    const float* __restrict__ x, const float* __restrict__ w,
    const float* __restrict__ b, __half* __restrict__ o) {
    int row = blockIdx.x;
    const float4* xr = (const float4*)(x + (size_t)row * D_);
    float ss = 0.f;
    #pragma unroll
    for (int i = threadIdx.x; i < D_ / 4; i += 256) {
        float4 v = xr[i];
        ss += v.x * v.x + v.y * v.y + v.z * v.z + v.w * v.w;
    }
    #pragma unroll
    for (int m = 16; m; m >>= 1) ss += __shfl_xor_sync(0xffffffffu, ss, m);
    __shared__ float red[8];
    if ((threadIdx.x & 31) == 0) red[threadIdx.x >> 5] = ss;
    __syncthreads();
    float tot = 0.f;
    #pragma unroll
    for (int i = 0; i < 8; i++) tot += red[i];
    float r = rsqrtf(tot * (1.0f / (float)D_) + EPS_);

    const float4* w4 = (const float4*)w;
    const float4* b4 = (const float4*)b;
    for (int i = threadIdx.x; i < D_ / 4; i += 256) {
        float4 v = xr[i], ww = w4[i], bb = b4[i];
        __half2 h01 = __floats2half2_rn(v.x * r * ww.x + bb.x, v.y * r * ww.y + bb.y);
        __half2 h23 = __floats2half2_rn(v.z * r * ww.z + bb.z, v.w * r * ww.w + bb.w);
        size_t base = (size_t)row * D_ + i * 4;
        *(__half2*)(o + base)     = h01;
        *(__half2*)(o + base + 2) = h23;
    }
}

// ---------------------------------------------------------------------------
// Kernel 3: fp16 HMMA GEMM  C[M,N] = A[M,K] @ B[N,K]^T, single product.
// BM=128, BN=256, BK=32, 512 threads, 4-stage cp.async pipeline.
// ---------------------------------------------------------------------------
#define BM 128
#define BN 256
#define BK 32
#define PAD 40
#define ATILE (BM * PAD * 2)                 // 10240 B
#define BTILE (BN * PAD * 2)                 // 20480 B
#define STAGE (ATILE + BTILE)                // 30720 B
#define GEMM_SMEM (4 * STAGE)                // 122880 B

__global__ __launch_bounds__(512, 1) void hgemm(
    const __half* __restrict__ A, const __half* __restrict__ B,
    float* __restrict__ C, int Kdim, int Nstride) {
    extern __shared__ char sm[];
    uint32_t smb = smem_u32(sm);
    const int tid = threadIdx.x;
    const int lane = tid & 31, wid = tid >> 5;
    const int wm = (wid >> 3) * 64;
    const int wn = (wid & 7) * 32;

    const size_t mBase = (size_t)blockIdx.y * BM;
    const size_t nBase = (size_t)blockIdx.x * BN;
    const __half* Ag = A + mBase * Kdim;
    const __half* Bg = B + nBase * Kdim;

    auto load = [&](int buf, int kc) {
        uint32_t base = smb + buf * STAGE;
        #pragma unroll
        for (int j = 0; j < 3; j++) {
            int c = tid + j * 512;          // 0..1535
            if (c < 512) {
                int row = c >> 2, col = (c & 3) << 3;
                cp16(base + (row * PAD + col) * 2, Ag + (size_t)row * Kdim + kc + col);
            } else {
                int cc = c - 512;
                int row = cc >> 2, col = (cc & 3) << 3;
                cp16(base + ATILE + (row * PAD + col) * 2, Bg + (size_t)row * Kdim + kc + col);
            }
        }
    };

    float acc[4][4][4];
    #pragma unroll
    for (int i = 0; i < 4; i++)
        #pragma unroll
        for (int j = 0; j < 4; j++)
            #pragma unroll
            for (int e = 0; e < 4; e++) acc[i][j][e] = 0.f;

    const int t8 = lane >> 3, r8 = lane & 7;
    const int aRow = wm + r8 + ((t8 & 1) << 3);
    const int aCol = (t8 >> 1) << 3;
    const int bRow = wn + r8 + ((t8 >> 1) << 3);
    const int bCol = (t8 & 1) << 3;

    const int KITERS = Kdim / BK;
    load(0, 0); CP_COMMIT();
    load(1, BK); CP_COMMIT();
    load(2, 2 * BK); CP_COMMIT();

    for (int it = 0; it < KITERS; ++it) {
        int rem = KITERS - 1 - it;
        if (rem >= 2) { CP_WAIT2(); } else if (rem == 1) { CP_WAIT1(); } else { CP_WAIT0(); }
        __syncthreads();

        uint32_t base = smb + (it & 3) * STAGE;
        uint32_t sA = base, sB = base + ATILE;

        #pragma unroll
        for (int ks = 0; ks < 2; ks++) {
            int k0 = ks << 4;
            uint32_t a[4][4];
            #pragma unroll
            for (int mf = 0; mf < 4; mf++)
                ldm4(a[mf], sA + ((aRow + mf * 16) * PAD + k0 + aCol) * 2);
            uint32_t b[4][2];
            #pragma unroll
            for (int nf2 = 0; nf2 < 2; nf2++) {
                uint32_t r[4];
                ldm4(r, sB + ((bRow + nf2 * 16) * PAD + k0 + bCol) * 2);
                b[nf2 * 2][0] = r[0]; b[nf2 * 2][1] = r[1];
                b[nf2 * 2 + 1][0] = r[2]; b[nf2 * 2 + 1][1] = r[3];
            }
            #pragma unroll
            for (int mf = 0; mf < 4; mf++)
                #pragma unroll
                for (int nf = 0; nf < 4; nf++)
                    mma_f16(acc[mf][nf], a[mf], b[nf]);
        }
        if (it + 3 < KITERS) {
            load((it + 3) & 3, (it + 3) * BK);
            CP_COMMIT();
        }
    }

    float* Cb = C + (mBase + wm) * Nstride + nBase + wn;
    const int er = lane >> 2, ec = (lane & 3) * 2;
    #pragma unroll
    for (int mf = 0; mf < 4; mf++) {
        #pragma unroll
        for (int nf = 0; nf < 4; nf++) {
            float* p0 = Cb + (size_t)(mf * 16 + er) * Nstride + nf * 8 + ec;
            p0[0] = acc[mf][nf][0];
            p0[1] = acc[mf][nf][1];
            float* p1 = p0 + 8 * (size_t)Nstride;
            p1[0] = acc[mf][nf][2];
            p1[1] = acc[mf][nf][3];
        }
    }
}

// ---------------------------------------------------------------------------
// Kernel 4: head prep: optional per-head RMS + partial RoPE, bf16 hi/lo split,
// layout transform [tok][h][HD] -> [b][h][t][HD]. One warp per row.
// ---------------------------------------------------------------------------
__global__ __launch_bounds__(256) void head_prep(
    const float* __restrict__ src_base, int H, int src_off,
    const float* __restrict__ w, const float* __restrict__ tcos,
    const float* __restrict__ tsin, int do_norm,
    __nv_bfloat16* __restrict__ dh, __nv_bfloat16* __restrict__ dl) {
    int rowi = blockIdx.x * 8 + (threadIdx.x >> 5);
    int lane = threadIdx.x & 31;
    int h = rowi % H;
    int tok = rowi / H;
    int t = tok & (T_ - 1);
    int b = tok >> 11;

    const float* p = src_base + (size_t)tok * NQKV + src_off + h * HD_;
    float v[5];
    #pragma unroll
    for (int i = 0; i < 5; i++) v[i] = p[lane + 32 * i];

    if (do_norm) {
        float ss = 0.f;
        #pragma unroll
        for (int i = 0; i < 5; i++) ss += v[i] * v[i];
        #pragma unroll
        for (int m = 16; m; m >>= 1) ss += __shfl_xor_sync(0xffffffffu, ss, m);
        float r = rsqrtf(ss * (1.0f / (float)HD_) + EPS_);
        const float* wh = w + h * HD_;
        #pragma unroll
        for (int i = 0; i < 5; i++) v[i] *= r * wh[lane + 32 * i];
        {   // RoPE d = lane (0..31)
            float partner = __shfl_xor_sync(0xffffffffu, v[0], 1);
            float rot = (lane & 1) ? partner : -partner;
            v[0] = v[0] * tcos[t * RD_ + lane] + rot * tsin[t * RD_ + lane];
        }
        {   // RoPE d = 32..39
            float partner = __shfl_xor_sync(0xffffffffu, v[1], 1);
            if (lane < 8) {
                int d = 32 + lane;
                float rot = (lane & 1) ? partner : -partner;
                v[1] = v[1] * tcos[t * RD_ + d] + rot * tsin[t * RD_ + d];
            }
        }
    }
    size_t dbase = ((size_t)(b * H + h) * T_ + t) * HD_;
    #pragma unroll
    for (int i = 0; i < 5; i++) {
        __nv_bfloat16 hh, ll;
        split2(v[i], hh, ll);
        dh[dbase + lane + 32 * i] = hh;
        dl[dbase + lane + 32 * i] = ll;
    }
}

// ---------------------------------------------------------------------------
// Kernel 5: HMMA causal flash attention. BQ=128, BKV=64, 256 threads (8 warps).
// Q/K/V bf16 hi/lo in smem (pad stride 168 elems, conflict-free ldmatrix).
// K double-buffered, V single-buffered. Output: fp16 single.
// ---------------------------------------------------------------------------
#define PADF 168
#define ROWB 336                    // PADF * 2 bytes
#define FQ_SZ 43008                 // 128 * ROWB
#define FK_SZ 21504                 // 64 * ROWB
#define FKBUF 86016                 // Qh + Ql
#define FVOFF 172032                // Qh+Ql + 2 K bufs (hi+lo each)
#define FLASH_SMEM 215040

__global__ __launch_bounds__(256, 1) void flash_hmma(
    const __nv_bfloat16* __restrict__ Qh_, const __nv_bfloat16* __restrict__ Ql_,
    const __nv_bfloat16* __restrict__ Kh_, const __nv_bfloat16* __restrict__ Kl_,
    const __nv_bfloat16* __restrict__ Vh_, const __nv_bfloat16* __restrict__ Vl_,
    __half* __restrict__ Of) {
    extern __shared__ char sm[];
    uint32_t smb = smem_u32(sm);
    const int qt = (T_ / 128 - 1) - blockIdx.x;   // heavy tiles first
    const int h = blockIdx.y, b = blockIdx.z;
    const int hk = h >> 2;
    const int tid = threadIdx.x, lane = tid & 31, wid = tid >> 5;

    const __nv_bfloat16* Qgh = Qh_ + ((size_t)(b * HQ_ + h) * T_ + qt * 128) * HD_;
    const __nv_bfloat16* Qgl = Ql_ + ((size_t)(b * HQ_ + h) * T_ + qt * 128) * HD_;
    const __nv_bfloat16* Kgh = Kh_ + (size_t)(b * HK_ + hk) * T_ * HD_;
    const __nv_bfloat16* Kgl = Kl_ + (size_t)(b * HK_ + hk) * T_ * HD_;
    const __nv_bfloat16* Vgh = Vh_ + (size_t)(b * HK_ + hk) * T_ * HD_;
    const __nv_bfloat16* Vgl = Vl_ + (size_t)(b * HK_ + hk) * T_ * HD_;

    // Q tile: 128x160 hi + lo
    #pragma unroll
    for (int j = 0; j < 20; j++) {
        int c = tid + j * 256;
        int hl = c >= 2560;
        int cc = c - hl * 2560;
        int row = cc / 20, col = (cc % 20) * 8;
        cp16(smb + hl * FQ_SZ + row * ROWB + col * 2,
             (hl ? Qgl : Qgh) + row * HD_ + col);
    }
    auto load_k = [&](int buf, int kt) {
        uint32_t base = smb + FKBUF + buf * (2 * FK_SZ);
        const __nv_bfloat16* s0 = Kgh + (size_t)kt * 64 * HD_;
        const __nv_bfloat16* s1 = Kgl + (size_t)kt * 64 * HD_;
        #pragma unroll
        for (int j = 0; j < 10; j++) {
            int c = tid + j * 256;
            int hl = c >= 1280;
            int cc = c - hl * 1280;
            int row = cc / 20, col = (cc % 20) * 8;
            cp16(base + hl * FK_SZ + row * ROWB + col * 2,
                 (hl ? s1 : s0) + row * HD_ + col);
        }
    };
    auto load_v = [&](int kt) {
        uint32_t base = smb + FVOFF;
        const __nv_bfloat16* s0 = Vgh + (size_t)kt * 64 * HD_;
        const __nv_bfloat16* s1 = Vgl + (size_t)kt * 64 * HD_;
        #pragma unroll
        for (int j = 0; j < 10; j++) {
            int c = tid + j * 256;
            int hl = c >= 1280;
            int cc = c - hl * 1280;
            int row = cc / 20, col = (cc % 20) * 8;
            cp16(base + hl * FK_SZ + row * ROWB + col * 2,
                 (hl ? s1 : s0) + row * HD_ + col);
        }
    };

    load_k(0, 0);
    CP_COMMIT();
    load_v(0);
    CP_COMMIT();

    float m0 = -1e30f, m1 = -1e30f, l0 = 0.f, l1 = 0.f;
    float o[20][4];
    #pragma unroll
    for (int f = 0; f < 20; f++)
        #pragma unroll
        for (int e = 0; e < 4; e++) o[f][e] = 0.f;

    const int gr = lane >> 2, ct = lane & 3;
    const int ldrow = (lane & 7) + ((lane >> 3) & 1) * 8;
    const int ldcol = ((lane >> 4) & 1) * 8;
    const uint32_t qh_b = smb + (wid * 16 + ldrow) * ROWB + ldcol * 2;
    const uint32_t ql_b = qh_b + FQ_SZ;
    const int rowg0 = qt * 128 + wid * 16 + gr;

    const int nkt = 2 * qt + 2;
    const float sc = 0.07905694150420949f * 1.4426950408889634f;  // scale*log2e

    for (int kt = 0; kt < nkt; kt++) {
        CP_WAIT1();
        __syncthreads();
        if (kt + 1 < nkt) { load_k((kt + 1) & 1, kt + 1); CP_COMMIT(); }

        // ---- S = Q K^T (hi/lo x3) ----
        float s[8][4];
        #pragma unroll
        for (int f = 0; f < 8; f++)
            #pragma unroll
            for (int e = 0; e < 4; e++) s[f][e] = 0.f;

        uint32_t kb = smb + FKBUF + (kt & 1) * (2 * FK_SZ) + ldrow * ROWB + ldcol * 2;
        #pragma unroll
        for (int ks = 0; ks < 10; ks++) {
            uint32_t ah[4], al[4];
            ldm4(ah, qh_b + ks * 32);
            ldm4(al, ql_b + ks * 32);
            #pragma unroll
            for (int ng = 0; ng < 4; ng++) {
                uint32_t rh[4], rl[4];
                ldm4(rh, kb + ng * 16 * ROWB + ks * 32);
                ldm4(rl, kb + FK_SZ + ng * 16 * ROWB + ks * 32);
                uint32_t bh0[2] = {rh[0], rh[2]}, bh1[2] = {rh[1], rh[3]};
                uint32_t bl0[2] = {rl[0], rl[2]}, bl1[2] = {rl[1], rl[3]};
                mma_bf16(s[2 * ng], ah, bh0);
                mma_bf16(s[2 * ng], ah, bl0);
                mma_bf16(s[2 * ng], al, bh0);
                mma_bf16(s[2 * ng + 1], ah, bh1);
                mma_bf16(s[2 * ng + 1], ah, bl1);
                mma_bf16(s[2 * ng + 1], al, bh1);
            }
        }

        // ---- mask + scale (base-2 domain) ----
        if (kt * 64 + 63 > qt * 128 + wid * 16) {
            #pragma unroll
            for (int f = 0; f < 8; f++) {
                int col = kt * 64 + f * 8 + 2 * ct;
                s[f][0] = (col     > rowg0)     ? -1e30f : s[f][0] * sc;
                s[f][1] = (col + 1 > rowg0)     ? -1e30f : s[f][1] * sc;
                s[f][2] = (col     > rowg0 + 8) ? -1e30f : s[f][2] * sc;
                s[f][3] = (col + 1 > rowg0 + 8) ? -1e30f : s[f][3] * sc;
            }
        } else {
            #pragma unroll
            for (int f = 0; f < 8; f++)
                #pragma unroll
                for (int e = 0; e < 4; e++) s[f][e] *= sc;
        }

        // ---- online softmax ----
        float r0 = -1e30f, r1 = -1e30f;
        #pragma unroll
        for (int f = 0; f < 8; f++) {
            r0 = fmaxf(r0, fmaxf(s[f][0], s[f][1]));
            r1 = fmaxf(r1, fmaxf(s[f][2], s[f][3]));
        }
        r0 = fmaxf(r0, __shfl_xor_sync(0xffffffffu, r0, 1));
        r0 = fmaxf(r0, __shfl_xor_sync(0xffffffffu, r0, 2));
        r1 = fmaxf(r1, __shfl_xor_sync(0xffffffffu, r1, 1));
        r1 = fmaxf(r1, __shfl_xor_sync(0xffffffffu, r1, 2));
        float mn0 = fmaxf(m0, r0), mn1 = fmaxf(m1, r1);
        float a0 = exp2p(m0 - mn0), a1 = exp2p(m1 - mn1);
        m0 = mn0; m1 = mn1;

        float rs0 = 0.f, rs1 = 0.f;
        uint32_t pA[8], pB[8], qA[8], qB[8];
        #pragma unroll
        for (int f = 0; f < 8; f++) {
            float p0 = exp2p(s[f][0] - mn0);
            float p1 = exp2p(s[f][1] - mn0);
            float p2 = exp2p(s[f][2] - mn1);
            float p3 = exp2p(s[f][3] - mn1);
            rs0 += p0 + p1; rs1 += p2 + p3;
            packhl(p0, p1, pA[f], qA[f]);
            packhl(p2, p3, pB[f], qB[f]);
        }
        rs0 += __shfl_xor_sync(0xffffffffu, rs0, 1);
        rs0 += __shfl_xor_sync(0xffffffffu, rs0, 2);
        rs1 += __shfl_xor_sync(0xffffffffu, rs1, 1);
        rs1 += __shfl_xor_sync(0xffffffffu, rs1, 2);
        l0 = l0 * a0 + rs0;
        l1 = l1 * a1 + rs1;
        #pragma unroll
        for (int f = 0; f < 20; f++) {
            o[f][0] *= a0; o[f][1] *= a0; o[f][2] *= a1; o[f][3] *= a1;
        }

        // ---- wait for V, then O += P V ----
        if (kt + 1 < nkt) { CP_WAIT1(); } else { CP_WAIT0(); }
        __syncthreads();

        #pragma unroll
        for (int ks = 0; ks < 4; ks++) {
            uint32_t a_h[4] = {pA[2 * ks], pB[2 * ks], pA[2 * ks + 1], pB[2 * ks + 1]};
            uint32_t a_l[4] = {qA[2 * ks], qB[2 * ks], qA[2 * ks + 1], qB[2 * ks + 1]};
            uint32_t vb = smb + FVOFF + (ks * 16 + ldrow) * ROWB + ldcol * 2;
            #pragma unroll
            for (int nb = 0; nb < 10; nb++) {
                uint32_t rh[4], rl[4];
                ldm4t(rh, vb + nb * 32);
                ldm4t(rl, vb + FK_SZ + nb * 32);
                uint32_t bh0[2] = {rh[0], rh[1]}, bh1[2] = {rh[2], rh[3]};
                uint32_t bl0[2] = {rl[0], rl[1]}, bl1[2] = {rl[2], rl[3]};
                mma_bf16(o[2 * nb], a_h, bh0);
                mma_bf16(o[2 * nb], a_h, bl0);
                mma_bf16(o[2 * nb], a_l, bh0);
                mma_bf16(o[2 * nb + 1], a_h, bh1);
                mma_bf16(o[2 * nb + 1], a_h, bl1);
                mma_bf16(o[2 * nb + 1], a_l, bh1);
            }
        }
        __syncthreads();          // V consumed
        if (kt + 1 < nkt) { load_v(kt + 1); CP_COMMIT(); }
    }

    // ---- epilogue: normalize, write fp16 [tok][D] ----
    float i0 = 1.f / l0, i1 = 1.f / l1;
    size_t rb0 = (size_t)(b * T_ + qt * 128 + wid * 16 + gr) * D_ + h * HD_;
    size_t rb1 = rb0 + 8 * (size_t)D_;
    #pragma unroll
    for (int f = 0; f < 20; f++) {
        int col = f * 8 + 2 * ct;
        __half2 h01 = __floats2half2_rn(o[f][0] * i0, o[f][1] * i0);
        __half2 h23 = __floats2half2_rn(o[f][2] * i1, o[f][3] * i1);
        *(uint32_t*)(Of + rb0 + col) = *(uint32_t*)&h01;
        *(uint32_t*)(Of + rb1 + col) = *(uint32_t*)&h23;
    }
}

// ---------------------------------------------------------------------------
// Host launch
// ---------------------------------------------------------------------------
extern "C" void kernel_launch(void* const* d_in, const int* in_sizes, int n_in,
                              void* d_out, int out_size) {
    const float* x      = (const float*)d_in[0];
    const float* wq     = (const float*)d_in[1];
    const float* wk     = (const float*)d_in[2];
    const float* wv     = (const float*)d_in[3];
    const float* wo     = (const float*)d_in[4];
    const float* norm_w = (const float*)d_in[5];
    const float* norm_b = (const float*)d_in[6];
    const float* qn_w   = (const float*)d_in[7];
    const float* kn_w   = (const float*)d_in[8];
    float* out = (float*)d_out;

    __half *af, *wtf, *wof, *of;
    __nv_bfloat16 *qh, *ql, *kh, *kl, *vh, *vl;
    float *qkv, *tcos, *tsin;
    cudaGetSymbolAddress((void**)&af,   g_af);
    cudaGetSymbolAddress((void**)&wtf,  g_wtf);
    cudaGetSymbolAddress((void**)&wof,  g_wof);
    cudaGetSymbolAddress((void**)&of,   g_of);
    cudaGetSymbolAddress((void**)&qh,   g_qh);
    cudaGetSymbolAddress((void**)&ql,   g_ql);
    cudaGetSymbolAddress((void**)&kh,   g_kh);
    cudaGetSymbolAddress((void**)&kl,   g_kl);
    cudaGetSymbolAddress((void**)&vh,   g_vh);
    cudaGetSymbolAddress((void**)&vl,   g_vl);
    cudaGetSymbolAddress((void**)&qkv,  g_qkv);
    cudaGetSymbolAddress((void**)&tcos, g_cos);
    cudaGetSymbolAddress((void**)&tsin, g_sin);

    cudaFuncSetAttribute(hgemm, cudaFuncAttributeMaxDynamicSharedMemorySize, GEMM_SMEM);
    cudaFuncSetAttribute(flash_hmma, cudaFuncAttributeMaxDynamicSharedMemorySize, FLASH_SMEM);

    // 0. fused weight transpose [wq|wk|wv] -> fp16
    wsplit_h<<<dim3(NQKV / 32, D_ / 32), 256>>>(wq, wk, wv, wtf);
    // 1. RMS layernorm -> fp16
    rmsnorm_kernel<<<NTOK, 256>>>(x, norm_w, norm_b, af);
    // 2. rope tables
    rope_table_kernel<<<(T_ * RD_ + 255) / 256, 256>>>(tcos, tsin);
    // 3. fused QKV projection (fp16 HMMA x1)  <-- profiled launch slot
    hgemm<<<dim3(NQKV / BN, NTOK / BM), 512, GEMM_SMEM>>>(af, wtf, qkv, D_, NQKV);
    // 4. wo transpose -> fp16
    wsplit_h<<<dim3(D_ / 32, D_ / 32), 256>>>(wo, wo, wo, wof);
    // 5-7. head prep: q norm+rope, k norm+rope, v split; layout [b][h][t][hd]
    head_prep<<<(NTOK * HQ_) / 8, 256>>>(qkv, HQ_, 0,    qn_w, tcos, tsin, 1, qh, ql);
    head_prep<<<(NTOK * HK_) / 8, 256>>>(qkv, HK_, KOFF, kn_w, tcos, tsin, 1, kh, kl);
    head_prep<<<(NTOK * HK_) / 8, 256>>>(qkv, HK_, VOFF, kn_w, tcos, tsin, 0, vh, vl);
    // 8. HMMA flash attention
    flash_hmma<<<dim3(T_ / 128, HQ_, B_), 256, FLASH_SMEM>>>(
        qh, ql, kh, kl, vh, vl, of);
    // 9. output projection (fp16 HMMA x1)
    hgemm<<<dim3(D_ / BN, NTOK / BM), 512, GEMM_SMEM>>>(of, wof, out, D_, D_);
}

// round 6
// speedup vs baseline: 8.0635x; 1.2371x over previous
#include <cuda_runtime.h>
#include <cuda_bf16.h>
#include <cuda_fp16.h>
#include <math.h>
#include <cstdint>

// Problem constants
#define B_  2
#define T_  2048
#define D_  5120
#define HQ_ 32
#define HK_ 8
#define HD_ 160
#define RD_ 40
#define NTOK (B_ * T_)          // 4096
#define EPS_ 1e-5f
#define NQKV 7680               // 5120 + 1280 + 1280
#define KOFF 5120
#define VOFF 6400

// ---------------------------------------------------------------------------
// PTX helpers (generic sm_80+ subset)
// ---------------------------------------------------------------------------
__device__ __forceinline__ uint32_t smem_u32(const void* p) {
    uint32_t a;
    asm("{ .reg .u64 t; cvta.to.shared.u64 t, %1; cvt.u32.u64 %0, t; }" : "=r"(a) : "l"(p));
    return a;
}
__device__ __forceinline__ void cp16(uint32_t s, const void* g) {
    asm volatile("cp.async.cg.shared.global [%0], [%1], 16;" :: "r"(s), "l"(g));
}
#define CP_COMMIT() asm volatile("cp.async.commit_group;")
#define CP_WAIT0()  asm volatile("cp.async.wait_group 0;")
#define CP_WAIT1()  asm volatile("cp.async.wait_group 1;")
#define CP_WAIT2()  asm volatile("cp.async.wait_group 2;")

__device__ __forceinline__ void ldm4(uint32_t* r, uint32_t addr) {
    asm volatile("ldmatrix.sync.aligned.m8n8.x4.shared.b16 {%0,%1,%2,%3}, [%4];"
                 : "=r"(r[0]), "=r"(r[1]), "=r"(r[2]), "=r"(r[3]) : "r"(addr));
}
__device__ __forceinline__ void ldm4t(uint32_t* r, uint32_t addr) {
    asm volatile("ldmatrix.sync.aligned.m8n8.x4.trans.shared.b16 {%0,%1,%2,%3}, [%4];"
                 : "=r"(r[0]), "=r"(r[1]), "=r"(r[2]), "=r"(r[3]) : "r"(addr));
}
__device__ __forceinline__ void mma_f16(float* c, const uint32_t* a, const uint32_t* b) {
    asm volatile(
        "mma.sync.aligned.m16n8k16.row.col.f32.f16.f16.f32 "
        "{%0,%1,%2,%3}, {%4,%5,%6,%7}, {%8,%9}, {%0,%1,%2,%3};"
        : "+f"(c[0]), "+f"(c[1]), "+f"(c[2]), "+f"(c[3])
        : "r"(a[0]), "r"(a[1]), "r"(a[2]), "r"(a[3]), "r"(b[0]), "r"(b[1]));
}
// fast exp2 on the FMA pipe (|err| ~3e-6), input <= 0
__device__ __forceinline__ float exp2p(float x) {
    x = fmaxf(x, -80.f);
    float r = rintf(x);
    float f = x - r;
    float p = 1.33335581e-3f;
    p = fmaf(p, f, 9.61812910e-3f);
    p = fmaf(p, f, 5.55041087e-2f);
    p = fmaf(p, f, 2.40226507e-1f);
    p = fmaf(p, f, 6.93147180e-1f);
    p = fmaf(p, f, 1.0f);
    return p * __int_as_float(((int)r + 127) << 23);
}

// ---------------------------------------------------------------------------
// Scratch (device globals)
// ---------------------------------------------------------------------------
__device__ __half g_af[NTOK * D_];               // nx fp16
__device__ __half g_wtf[NQKV * D_];              // [wq|wk|wv]^T fp16 [7680,5120]
__device__ __half g_wof[D_ * D_];                // wo^T fp16 [5120,5120]
__device__ float  g_qkv[NTOK * NQKV];            // fused qkv output (fp32)
__device__ __half g_qf[NTOK * HQ_ * HD_];        // q head-major [B,HQ,T,HD] fp16
__device__ __half g_kf[NTOK * HK_ * HD_];        // k head-major [B,HK,T,HD] fp16
__device__ __half g_vf[NTOK * HK_ * HD_];        // v head-major fp16
__device__ __half g_of[NTOK * D_];               // attn out fp16 [tok, D]
__device__ float g_cos[T_ * RD_];
__device__ float g_sin[T_ * RD_];

// ---------------------------------------------------------------------------
// Kernel 0: RoPE tables (fp64)
// ---------------------------------------------------------------------------
__global__ void rope_table_kernel(float* __restrict__ tc, float* __restrict__ ts) {
    int idx = blockIdx.x * 256 + threadIdx.x;
    if (idx >= T_ * RD_) return;
    int t = idx / RD_;
    int i = idx % RD_;
    int f = i % 20;
    double invf = pow(5000000.0, -(double)f / 20.0);
    double ang = (double)t * invf;
    tc[idx] = (float)cos(ang);
    ts[idx] = (float)sin(ang);
}

// ---------------------------------------------------------------------------
// Kernel 1: weight transpose -> fp16, 3 sources fused (wq|wk|wv column blocks)
// ---------------------------------------------------------------------------
__global__ __launch_bounds__(256) void wsplit_h(
    const float* __restrict__ w0, const float* __restrict__ w1,
    const float* __restrict__ w2, __half* __restrict__ dst) {
    __shared__ float tile[32][33];
    int kb = blockIdx.y * 32, nb = blockIdx.x * 32;
    const float* src; int N; int nloc;
    if (nb < KOFF)      { src = w0; N = D_;        nloc = nb; }
    else if (nb < VOFF) { src = w1; N = HK_ * HD_; nloc = nb - KOFF; }
    else                { src = w2; N = HK_ * HD_; nloc = nb - VOFF; }
    int tx = threadIdx.x & 31, ty = threadIdx.x >> 5;
    #pragma unroll
    for (int i = 0; i < 4; i++)
        tile[ty + i * 8][tx] = src[(size_t)(kb + ty + i * 8) * N + nloc + tx];
    __syncthreads();
    #pragma unroll
    for (int i = 0; i < 4; i++) {
        int r = ty + i * 8;
        dst[(size_t)(nb + r) * D_ + kb + tx] = __float2half_rn(tile[tx][r]);
    }
}

// ---------------------------------------------------------------------------
// Kernel 2: RMS layernorm -> fp16
// ---------------------------------------------------------------------------
__global__ __launch_bounds__(256) void rmsnorm_kernel(
    const float* __restrict__ x, const float* __restrict__ w,
    const float* __restrict__ b, __half* __restrict__ o) {
    int row = blockIdx.x;
    const float4* xr = (const float4*)(x + (size_t)row * D_);
    float ss = 0.f;
    #pragma unroll
    for (int i = threadIdx.x; i < D_ / 4; i += 256) {
        float4 v = xr[i];
        ss += v.x * v.x + v.y * v.y + v.z * v.z + v.w * v.w;
    }
    #pragma unroll
    for (int m = 16; m; m >>= 1) ss += __shfl_xor_sync(0xffffffffu, ss, m);
    __shared__ float red[8];
    if ((threadIdx.x & 31) == 0) red[threadIdx.x >> 5] = ss;
    __syncthreads();
    float tot = 0.f;
    #pragma unroll
    for (int i = 0; i < 8; i++) tot += red[i];
    float r = rsqrtf(tot * (1.0f / (float)D_) + EPS_);

    const float4* w4 = (const float4*)w;
    const float4* b4 = (const float4*)b;
    for (int i = threadIdx.x; i < D_ / 4; i += 256) {
        float4 v = xr[i], ww = w4[i], bb = b4[i];
        __half2 h01 = __floats2half2_rn(v.x * r * ww.x + bb.x, v.y * r * ww.y + bb.y);
        __half2 h23 = __floats2half2_rn(v.z * r * ww.z + bb.z, v.w * r * ww.w + bb.w);
        size_t base = (size_t)row * D_ + i * 4;
        *(__half2*)(o + base)     = h01;
        *(__half2*)(o + base + 2) = h23;
    }
}

// ---------------------------------------------------------------------------
// Kernel 3: fp16 HMMA GEMM (unchanged from R5)
// ---------------------------------------------------------------------------
#define BM 128
#define BN 256
#define BK 32
#define PAD 40
#define ATILE (BM * PAD * 2)
#define BTILE (BN * PAD * 2)
#define STAGE (ATILE + BTILE)
#define GEMM_SMEM (4 * STAGE)

__global__ __launch_bounds__(512, 1) void hgemm(
    const __half* __restrict__ A, const __half* __restrict__ B,
    float* __restrict__ C, int Kdim, int Nstride) {
    extern __shared__ char sm[];
    uint32_t smb = smem_u32(sm);
    const int tid = threadIdx.x;
    const int lane = tid & 31, wid = tid >> 5;
    const int wm = (wid >> 3) * 64;
    const int wn = (wid & 7) * 32;

    const size_t mBase = (size_t)blockIdx.y * BM;
    const size_t nBase = (size_t)blockIdx.x * BN;
    const __half* Ag = A + mBase * Kdim;
    const __half* Bg = B + nBase * Kdim;

    auto load = [&](int buf, int kc) {
        uint32_t base = smb + buf * STAGE;
        #pragma unroll
        for (int j = 0; j < 3; j++) {
            int c = tid + j * 512;
            if (c < 512) {
                int row = c >> 2, col = (c & 3) << 3;
                cp16(base + (row * PAD + col) * 2, Ag + (size_t)row * Kdim + kc + col);
            } else {
                int cc = c - 512;
                int row = cc >> 2, col = (cc & 3) << 3;
                cp16(base + ATILE + (row * PAD + col) * 2, Bg + (size_t)row * Kdim + kc + col);
            }
        }
    };

    float acc[4][4][4];
    #pragma unroll
    for (int i = 0; i < 4; i++)
        #pragma unroll
        for (int j = 0; j < 4; j++)
            #pragma unroll
            for (int e = 0; e < 4; e++) acc[i][j][e] = 0.f;

    const int t8 = lane >> 3, r8 = lane & 7;
    const int aRow = wm + r8 + ((t8 & 1) << 3);
    const int aCol = (t8 >> 1) << 3;
    const int bRow = wn + r8 + ((t8 >> 1) << 3);
    const int bCol = (t8 & 1) << 3;

    const int KITERS = Kdim / BK;
    load(0, 0); CP_COMMIT();
    load(1, BK); CP_COMMIT();
    load(2, 2 * BK); CP_COMMIT();

    for (int it = 0; it < KITERS; ++it) {
        int rem = KITERS - 1 - it;
        if (rem >= 2) { CP_WAIT2(); } else if (rem == 1) { CP_WAIT1(); } else { CP_WAIT0(); }
        __syncthreads();

        uint32_t base = smb + (it & 3) * STAGE;
        uint32_t sA = base, sB = base + ATILE;

        #pragma unroll
        for (int ks = 0; ks < 2; ks++) {
            int k0 = ks << 4;
            uint32_t a[4][4];
            #pragma unroll
            for (int mf = 0; mf < 4; mf++)
                ldm4(a[mf], sA + ((aRow + mf * 16) * PAD + k0 + aCol) * 2);
            uint32_t b[4][2];
            #pragma unroll
            for (int nf2 = 0; nf2 < 2; nf2++) {
                uint32_t r[4];
                ldm4(r, sB + ((bRow + nf2 * 16) * PAD + k0 + bCol) * 2);
                b[nf2 * 2][0] = r[0]; b[nf2 * 2][1] = r[1];
                b[nf2 * 2 + 1][0] = r[2]; b[nf2 * 2 + 1][1] = r[3];
            }
            #pragma unroll
            for (int mf = 0; mf < 4; mf++)
                #pragma unroll
                for (int nf = 0; nf < 4; nf++)
                    mma_f16(acc[mf][nf], a[mf], b[nf]);
        }
        if (it + 3 < KITERS) {
            load((it + 3) & 3, (it + 3) * BK);
            CP_COMMIT();
        }
    }

    float* Cb = C + (mBase + wm) * Nstride + nBase + wn;
    const int er = lane >> 2, ec = (lane & 3) * 2;
    #pragma unroll
    for (int mf = 0; mf < 4; mf++) {
        #pragma unroll
        for (int nf = 0; nf < 4; nf++) {
            float* p0 = Cb + (size_t)(mf * 16 + er) * Nstride + nf * 8 + ec;
            p0[0] = acc[mf][nf][0];
            p0[1] = acc[mf][nf][1];
            float* p1 = p0 + 8 * (size_t)Nstride;
            p1[0] = acc[mf][nf][2];
            p1[1] = acc[mf][nf][3];
        }
    }
}

// ---------------------------------------------------------------------------
// Kernel 4: head prep: optional per-head RMS + partial RoPE -> fp16,
// layout transform [tok][h][HD] -> [b][h][t][HD]. One warp per row.
// ---------------------------------------------------------------------------
__global__ __launch_bounds__(256) void head_prep(
    const float* __restrict__ src_base, int H, int src_off,
    const float* __restrict__ w, const float* __restrict__ tcos,
    const float* __restrict__ tsin, int do_norm, __half* __restrict__ dst) {
    int rowi = blockIdx.x * 8 + (threadIdx.x >> 5);
    int lane = threadIdx.x & 31;
    int h = rowi % H;
    int tok = rowi / H;
    int t = tok & (T_ - 1);
    int b = tok >> 11;

    const float* p = src_base + (size_t)tok * NQKV + src_off + h * HD_;
    float v[5];
    #pragma unroll
    for (int i = 0; i < 5; i++) v[i] = p[lane + 32 * i];

    if (do_norm) {
        float ss = 0.f;
        #pragma unroll
        for (int i = 0; i < 5; i++) ss += v[i] * v[i];
        #pragma unroll
        for (int m = 16; m; m >>= 1) ss += __shfl_xor_sync(0xffffffffu, ss, m);
        float r = rsqrtf(ss * (1.0f / (float)HD_) + EPS_);
        const float* wh = w + h * HD_;
        #pragma unroll
        for (int i = 0; i < 5; i++) v[i] *= r * wh[lane + 32 * i];
        {   // RoPE d = lane (0..31)
            float partner = __shfl_xor_sync(0xffffffffu, v[0], 1);
            float rot = (lane & 1) ? partner : -partner;
            v[0] = v[0] * tcos[t * RD_ + lane] + rot * tsin[t * RD_ + lane];
        }
        {   // RoPE d = 32..39
            float partner = __shfl_xor_sync(0xffffffffu, v[1], 1);
            if (lane < 8) {
                int d = 32 + lane;
                float rot = (lane & 1) ? partner : -partner;
                v[1] = v[1] * tcos[t * RD_ + d] + rot * tsin[t * RD_ + d];
            }
        }
    }
    size_t dbase = ((size_t)(b * H + h) * T_ + t) * HD_;
    #pragma unroll
    for (int i = 0; i < 5; i++)
        dst[dbase + lane + 32 * i] = __float2half_rn(v[i]);
}

// ---------------------------------------------------------------------------
// Kernel 5: fp16 HMMA causal flash attention. BQ=128, BKV=64, 256 thr (8 warps).
// Single fp16 operands. Q resident; K and V double-buffered via cp.async.
// Pad stride 168 halves -> conflict-free ldmatrix.
// ---------------------------------------------------------------------------
#define ROWB 336                    // 168 halves * 2 bytes
#define FQ_SZ 43008                 // 128 * ROWB
#define FK_SZ 21504                 // 64 * ROWB
#define FKOFF FQ_SZ                 // K bufs
#define FVOFF (FQ_SZ + 2 * FK_SZ)   // V bufs
#define FLASH_SMEM (FQ_SZ + 4 * FK_SZ)   // 129024

__global__ __launch_bounds__(256, 1) void flash_hmma(
    const __half* __restrict__ Qf, const __half* __restrict__ Kf,
    const __half* __restrict__ Vf, __half* __restrict__ Of) {
    extern __shared__ char sm[];
    uint32_t smb = smem_u32(sm);
    const int qt = (T_ / 128 - 1) - blockIdx.x;   // heavy tiles first
    const int h = blockIdx.y, b = blockIdx.z;
    const int hk = h >> 2;
    const int tid = threadIdx.x, lane = tid & 31, wid = tid >> 5;

    const __half* Qg = Qf + ((size_t)(b * HQ_ + h) * T_ + qt * 128) * HD_;
    const __half* Kg = Kf + (size_t)(b * HK_ + hk) * T_ * HD_;
    const __half* Vg = Vf + (size_t)(b * HK_ + hk) * T_ * HD_;

    // Q tile: 128 x 160 fp16, 2560 16B-chunks, 10 per thread
    #pragma unroll
    for (int j = 0; j < 10; j++) {
        int c = tid + j * 256;
        int row = c / 20, col = (c % 20) * 8;
        cp16(smb + row * ROWB + col * 2, Qg + row * HD_ + col);
    }
    auto load_k = [&](int buf, int kt) {
        uint32_t base = smb + FKOFF + buf * FK_SZ;
        const __half* s = Kg + (size_t)kt * 64 * HD_;
        #pragma unroll
        for (int j = 0; j < 5; j++) {
            int c = tid + j * 256;
            int row = c / 20, col = (c % 20) * 8;
            cp16(base + row * ROWB + col * 2, s + row * HD_ + col);
        }
    };
    auto load_v = [&](int buf, int kt) {
        uint32_t base = smb + FVOFF + buf * FK_SZ;
        const __half* s = Vg + (size_t)kt * 64 * HD_;
        #pragma unroll
        for (int j = 0; j < 5; j++) {
            int c = tid + j * 256;
            int row = c / 20, col = (c % 20) * 8;
            cp16(base + row * ROWB + col * 2, s + row * HD_ + col);
        }
    };

    load_k(0, 0); CP_COMMIT();      // group: Q + K0
    load_v(0, 0); CP_COMMIT();      // group: V0

    float m0 = -1e30f, m1 = -1e30f, l0 = 0.f, l1 = 0.f;
    float o[20][4];
    #pragma unroll
    for (int f = 0; f < 20; f++)
        #pragma unroll
        for (int e = 0; e < 4; e++) o[f][e] = 0.f;

    const int gr = lane >> 2, ct = lane & 3;
    const int ldrow = (lane & 7) + ((lane >> 3) & 1) * 8;
    const int ldcol = ((lane >> 4) & 1) * 8;
    const uint32_t q_b = smb + (wid * 16 + ldrow) * ROWB + ldcol * 2;
    const int rowg0 = qt * 128 + wid * 16 + gr;

    const int nkt = 2 * qt + 2;
    const float sc = 0.07905694150420949f * 1.4426950408889634f;  // scale*log2e

    for (int kt = 0; kt < nkt; kt++) {
        // prefetch kt+1 into the other buffer, then wait for kt's K+V
        if (kt + 1 < nkt) {
            load_k((kt + 1) & 1, kt + 1); CP_COMMIT();
            load_v((kt + 1) & 1, kt + 1); CP_COMMIT();
            CP_WAIT2();
        } else {
            CP_WAIT0();
        }
        __syncthreads();

        // ---- S = Q K^T (single fp16) ----
        float s[8][4];
        #pragma unroll
        for (int f = 0; f < 8; f++)
            #pragma unroll
            for (int e = 0; e < 4; e++) s[f][e] = 0.f;

        uint32_t kb = smb + FKOFF + (kt & 1) * FK_SZ + ldrow * ROWB + ldcol * 2;
        #pragma unroll
        for (int ks = 0; ks < 10; ks++) {
            uint32_t a[4];
            ldm4(a, q_b + ks * 32);
            #pragma unroll
            for (int ng = 0; ng < 4; ng++) {
                uint32_t r[4];
                ldm4(r, kb + ng * 16 * ROWB + ks * 32);
                uint32_t b0[2] = {r[0], r[2]}, b1[2] = {r[1], r[3]};
                mma_f16(s[2 * ng], a, b0);
                mma_f16(s[2 * ng + 1], a, b1);
            }
        }

        // ---- mask + scale (base-2 domain) ----
        if (kt * 64 + 63 > qt * 128 + wid * 16) {
            #pragma unroll
            for (int f = 0; f < 8; f++) {
                int col = kt * 64 + f * 8 + 2 * ct;
                s[f][0] = (col     > rowg0)     ? -1e30f : s[f][0] * sc;
                s[f][1] = (col + 1 > rowg0)     ? -1e30f : s[f][1] * sc;
                s[f][2] = (col     > rowg0 + 8) ? -1e30f : s[f][2] * sc;
                s[f][3] = (col + 1 > rowg0 + 8) ? -1e30f : s[f][3] * sc;
            }
        } else {
            #pragma unroll
            for (int f = 0; f < 8; f++)
                #pragma unroll
                for (int e = 0; e < 4; e++) s[f][e] *= sc;
        }

        // ---- online softmax ----
        float r0 = -1e30f, r1 = -1e30f;
        #pragma unroll
        for (int f = 0; f < 8; f++) {
            r0 = fmaxf(r0, fmaxf(s[f][0], s[f][1]));
            r1 = fmaxf(r1, fmaxf(s[f][2], s[f][3]));
        }
        r0 = fmaxf(r0, __shfl_xor_sync(0xffffffffu, r0, 1));
        r0 = fmaxf(r0, __shfl_xor_sync(0xffffffffu, r0, 2));
        r1 = fmaxf(r1, __shfl_xor_sync(0xffffffffu, r1, 1));
        r1 = fmaxf(r1, __shfl_xor_sync(0xffffffffu, r1, 2));
        float mn0 = fmaxf(m0, r0), mn1 = fmaxf(m1, r1);
        float a0 = exp2p(m0 - mn0), a1 = exp2p(m1 - mn1);
        m0 = mn0; m1 = mn1;

        float rs0 = 0.f, rs1 = 0.f;
        uint32_t pA[8], pB[8];
        #pragma unroll
        for (int f = 0; f < 8; f++) {
            float p0 = exp2p(s[f][0] - mn0);
            float p1 = exp2p(s[f][1] - mn0);
            float p2 = exp2p(s[f][2] - mn1);
            float p3 = exp2p(s[f][3] - mn1);
            rs0 += p0 + p1; rs1 += p2 + p3;
            __half2 hA = __floats2half2_rn(p0, p1);
            __half2 hB = __floats2half2_rn(p2, p3);
            pA[f] = *(uint32_t*)&hA;
            pB[f] = *(uint32_t*)&hB;
        }
        rs0 += __shfl_xor_sync(0xffffffffu, rs0, 1);
        rs0 += __shfl_xor_sync(0xffffffffu, rs0, 2);
        rs1 += __shfl_xor_sync(0xffffffffu, rs1, 1);
        rs1 += __shfl_xor_sync(0xffffffffu, rs1, 2);
        l0 = l0 * a0 + rs0;
        l1 = l1 * a1 + rs1;
        #pragma unroll
        for (int f = 0; f < 20; f++) {
            o[f][0] *= a0; o[f][1] *= a0; o[f][2] *= a1; o[f][3] *= a1;
        }

        // ---- O += P V (single fp16) ----
        uint32_t vbase = smb + FVOFF + (kt & 1) * FK_SZ;
        #pragma unroll
        for (int ks = 0; ks < 4; ks++) {
            uint32_t a[4] = {pA[2 * ks], pB[2 * ks], pA[2 * ks + 1], pB[2 * ks + 1]};
            uint32_t vb = vbase + (ks * 16 + ldrow) * ROWB + ldcol * 2;
            #pragma unroll
            for (int nb = 0; nb < 10; nb++) {
                uint32_t r[4];
                ldm4t(r, vb + nb * 32);
                uint32_t b0[2] = {r[0], r[1]}, b1[2] = {r[2], r[3]};
                mma_f16(o[2 * nb], a, b0);
                mma_f16(o[2 * nb + 1], a, b1);
            }
        }
        __syncthreads();    // everyone done reading buf (kt&1) before next prefetch
    }

    // ---- epilogue: normalize, write fp16 [tok][D] ----
    float i0 = 1.f / l0, i1 = 1.f / l1;
    size_t rb0 = (size_t)(b * T_ + qt * 128 + wid * 16 + gr) * D_ + h * HD_;
    size_t rb1 = rb0 + 8 * (size_t)D_;
    #pragma unroll
    for (int f = 0; f < 20; f++) {
        int col = f * 8 + 2 * ct;
        __half2 h01 = __floats2half2_rn(o[f][0] * i0, o[f][1] * i0);
        __half2 h23 = __floats2half2_rn(o[f][2] * i1, o[f][3] * i1);
        *(uint32_t*)(Of + rb0 + col) = *(uint32_t*)&h01;
        *(uint32_t*)(Of + rb1 + col) = *(uint32_t*)&h23;
    }
}

// ---------------------------------------------------------------------------
// Host launch
// ---------------------------------------------------------------------------
extern "C" void kernel_launch(void* const* d_in, const int* in_sizes, int n_in,
                              void* d_out, int out_size) {
    const float* x      = (const float*)d_in[0];
    const float* wq     = (const float*)d_in[1];
    const float* wk     = (const float*)d_in[2];
    const float* wv     = (const float*)d_in[3];
    const float* wo     = (const float*)d_in[4];
    const float* norm_w = (const float*)d_in[5];
    const float* norm_b = (const float*)d_in[6];
    const float* qn_w   = (const float*)d_in[7];
    const float* kn_w   = (const float*)d_in[8];
    float* out = (float*)d_out;

    __half *af, *wtf, *wof, *of, *qf, *kf, *vf;
    float *qkv, *tcos, *tsin;
    cudaGetSymbolAddress((void**)&af,   g_af);
    cudaGetSymbolAddress((void**)&wtf,  g_wtf);
    cudaGetSymbolAddress((void**)&wof,  g_wof);
    cudaGetSymbolAddress((void**)&of,   g_of);
    cudaGetSymbolAddress((void**)&qf,   g_qf);
    cudaGetSymbolAddress((void**)&kf,   g_kf);
    cudaGetSymbolAddress((void**)&vf,   g_vf);
    cudaGetSymbolAddress((void**)&qkv,  g_qkv);
    cudaGetSymbolAddress((void**)&tcos, g_cos);
    cudaGetSymbolAddress((void**)&tsin, g_sin);

    cudaFuncSetAttribute(hgemm, cudaFuncAttributeMaxDynamicSharedMemorySize, GEMM_SMEM);
    cudaFuncSetAttribute(flash_hmma, cudaFuncAttributeMaxDynamicSharedMemorySize, FLASH_SMEM);

    // 0. fused weight transpose [wq|wk|wv] -> fp16
    wsplit_h<<<dim3(NQKV / 32, D_ / 32), 256>>>(wq, wk, wv, wtf);
    // 1. RMS layernorm -> fp16
    rmsnorm_kernel<<<NTOK, 256>>>(x, norm_w, norm_b, af);
    // 2. rope tables
    rope_table_kernel<<<(T_ * RD_ + 255) / 256, 256>>>(tcos, tsin);
    // 3. fused QKV projection (fp16 HMMA)
    hgemm<<<dim3(NQKV / BN, NTOK / BM), 512, GEMM_SMEM>>>(af, wtf, qkv, D_, NQKV);
    // 4. wo transpose -> fp16
    wsplit_h<<<dim3(D_ / 32, D_ / 32), 256>>>(wo, wo, wo, wof);
    // 5-7. head prep: q norm+rope, k norm+rope, v; layout [b][h][t][hd] fp16
    head_prep<<<(NTOK * HQ_) / 8, 256>>>(qkv, HQ_, 0,    qn_w, tcos, tsin, 1, qf);
    head_prep<<<(NTOK * HK_) / 8, 256>>>(qkv, HK_, KOFF, kn_w, tcos, tsin, 1, kf);
    head_prep<<<(NTOK * HK_) / 8, 256>>>(qkv, HK_, VOFF, kn_w, tcos, tsin, 0, vf);
    // 8. fp16 HMMA flash attention
    flash_hmma<<<dim3(T_ / 128, HQ_, B_), 256, FLASH_SMEM>>>(qf, kf, vf, of);
    // 9. output projection (fp16 HMMA)
    hgemm<<<dim3(D_ / BN, NTOK / BM), 512, GEMM_SMEM>>>(of, wof, out, D_, D_);
}

// round 7
// speedup vs baseline: 8.8775x; 1.1010x over previous
#include <cuda_runtime.h>
#include <cuda_bf16.h>
#include <cuda_fp16.h>
#include <math.h>
#include <cstdint>

// Problem constants
#define B_  2
#define T_  2048
#define D_  5120
#define HQ_ 32
#define HK_ 8
#define HD_ 160
#define RD_ 40
#define NTOK (B_ * T_)          // 4096
#define EPS_ 1e-5f
#define NQKV 7680               // 5120 + 1280 + 1280
#define KOFF 5120
#define VOFF 6400

// ---------------------------------------------------------------------------
// PTX helpers (generic sm_80+ subset)
// ---------------------------------------------------------------------------
__device__ __forceinline__ uint32_t smem_u32(const void* p) {
    uint32_t a;
    asm("{ .reg .u64 t; cvta.to.shared.u64 t, %1; cvt.u32.u64 %0, t; }" : "=r"(a) : "l"(p));
    return a;
}
__device__ __forceinline__ void cp16(uint32_t s, const void* g) {
    asm volatile("cp.async.cg.shared.global [%0], [%1], 16;" :: "r"(s), "l"(g));
}
#define CP_COMMIT() asm volatile("cp.async.commit_group;")
#define CP_WAIT0()  asm volatile("cp.async.wait_group 0;")
#define CP_WAIT1()  asm volatile("cp.async.wait_group 1;")
#define CP_WAIT2()  asm volatile("cp.async.wait_group 2;")

__device__ __forceinline__ void ldm4(uint32_t* r, uint32_t addr) {
    asm volatile("ldmatrix.sync.aligned.m8n8.x4.shared.b16 {%0,%1,%2,%3}, [%4];"
                 : "=r"(r[0]), "=r"(r[1]), "=r"(r[2]), "=r"(r[3]) : "r"(addr));
}
__device__ __forceinline__ void ldm4t(uint32_t* r, uint32_t addr) {
    asm volatile("ldmatrix.sync.aligned.m8n8.x4.trans.shared.b16 {%0,%1,%2,%3}, [%4];"
                 : "=r"(r[0]), "=r"(r[1]), "=r"(r[2]), "=r"(r[3]) : "r"(addr));
}
__device__ __forceinline__ void mma_f16(float* c, const uint32_t* a, const uint32_t* b) {
    asm volatile(
        "mma.sync.aligned.m16n8k16.row.col.f32.f16.f16.f32 "
        "{%0,%1,%2,%3}, {%4,%5,%6,%7}, {%8,%9}, {%0,%1,%2,%3};"
        : "+f"(c[0]), "+f"(c[1]), "+f"(c[2]), "+f"(c[3])
        : "r"(a[0]), "r"(a[1]), "r"(a[2]), "r"(a[3]), "r"(b[0]), "r"(b[1]));
}
// fast exp2 on the FMA pipe (|err| ~3e-6), input <= 0
__device__ __forceinline__ float exp2p(float x) {
    x = fmaxf(x, -80.f);
    float r = rintf(x);
    float f = x - r;
    float p = 1.33335581e-3f;
    p = fmaf(p, f, 9.61812910e-3f);
    p = fmaf(p, f, 5.55041087e-2f);
    p = fmaf(p, f, 2.40226507e-1f);
    p = fmaf(p, f, 6.93147180e-1f);
    p = fmaf(p, f, 1.0f);
    return p * __int_as_float(((int)r + 127) << 23);
}

// ---------------------------------------------------------------------------
// Scratch (device globals)
// ---------------------------------------------------------------------------
__device__ __half g_af[NTOK * D_];               // nx fp16
__device__ __half g_wtf[NQKV * D_];              // [wq|wk|wv]^T fp16 [7680,5120]
__device__ __half g_wof[D_ * D_];                // wo^T fp16 [5120,5120]
__device__ float  g_qkv[NTOK * NQKV];            // fused qkv output (fp32)
__device__ __half g_qf[NTOK * HQ_ * HD_];        // q head-major [B,HQ,T,HD] fp16
__device__ __half g_kf[NTOK * HK_ * HD_];        // k head-major [B,HK,T,HD] fp16
__device__ __half g_vf[NTOK * HK_ * HD_];        // v head-major fp16
__device__ __half g_of[NTOK * D_];               // attn out fp16 [tok, D]
__device__ float g_cos[T_ * RD_];
__device__ float g_sin[T_ * RD_];

// ---------------------------------------------------------------------------
// Kernel 0: RoPE tables (fp64)
// ---------------------------------------------------------------------------
__global__ void rope_table_kernel(float* __restrict__ tc, float* __restrict__ ts) {
    int idx = blockIdx.x * 256 + threadIdx.x;
    if (idx >= T_ * RD_) return;
    int t = idx / RD_;
    int i = idx % RD_;
    int f = i % 20;
    double invf = pow(5000000.0, -(double)f / 20.0);
    double ang = (double)t * invf;
    tc[idx] = (float)cos(ang);
    ts[idx] = (float)sin(ang);
}

// ---------------------------------------------------------------------------
// Kernel 1: weight transpose -> fp16, 3 sources fused (wq|wk|wv column blocks)
// ---------------------------------------------------------------------------
__global__ __launch_bounds__(256) void wsplit_h(
    const float* __restrict__ w0, const float* __restrict__ w1,
    const float* __restrict__ w2, __half* __restrict__ dst) {
    __shared__ float tile[32][33];
    int kb = blockIdx.y * 32, nb = blockIdx.x * 32;
    const float* src; int N; int nloc;
    if (nb < KOFF)      { src = w0; N = D_;        nloc = nb; }
    else if (nb < VOFF) { src = w1; N = HK_ * HD_; nloc = nb - KOFF; }
    else                { src = w2; N = HK_ * HD_; nloc = nb - VOFF; }
    int tx = threadIdx.x & 31, ty = threadIdx.x >> 5;
    #pragma unroll
    for (int i = 0; i < 4; i++)
        tile[ty + i * 8][tx] = src[(size_t)(kb + ty + i * 8) * N + nloc + tx];
    __syncthreads();
    #pragma unroll
    for (int i = 0; i < 4; i++) {
        int r = ty + i * 8;
        dst[(size_t)(nb + r) * D_ + kb + tx] = __float2half_rn(tile[tx][r]);
    }
}

// ---------------------------------------------------------------------------
// Kernel 2: RMS layernorm -> fp16
// ---------------------------------------------------------------------------
__global__ __launch_bounds__(256) void rmsnorm_kernel(
    const float* __restrict__ x, const float* __restrict__ w,
    const float* __restrict__ b, __half* __restrict__ o) {
    int row = blockIdx.x;
    const float4* xr = (const float4*)(x + (size_t)row * D_);
    float ss = 0.f;
    #pragma unroll
    for (int i = threadIdx.x; i < D_ / 4; i += 256) {
        float4 v = xr[i];
        ss += v.x * v.x + v.y * v.y + v.z * v.z + v.w * v.w;
    }
    #pragma unroll
    for (int m = 16; m; m >>= 1) ss += __shfl_xor_sync(0xffffffffu, ss, m);
    __shared__ float red[8];
    if ((threadIdx.x & 31) == 0) red[threadIdx.x >> 5] = ss;
    __syncthreads();
    float tot = 0.f;
    #pragma unroll
    for (int i = 0; i < 8; i++) tot += red[i];
    float r = rsqrtf(tot * (1.0f / (float)D_) + EPS_);

    const float4* w4 = (const float4*)w;
    const float4* b4 = (const float4*)b;
    for (int i = threadIdx.x; i < D_ / 4; i += 256) {
        float4 v = xr[i], ww = w4[i], bb = b4[i];
        __half2 h01 = __floats2half2_rn(v.x * r * ww.x + bb.x, v.y * r * ww.y + bb.y);
        __half2 h23 = __floats2half2_rn(v.z * r * ww.z + bb.z, v.w * r * ww.w + bb.w);
        size_t base = (size_t)row * D_ + i * 4;
        *(__half2*)(o + base)     = h01;
        *(__half2*)(o + base + 2) = h23;
    }
}

// ---------------------------------------------------------------------------
// Kernel 3: fp16 HMMA GEMM. BM=128, BN=128, BK=32, 256 threads, 4-stage
// cp.async pipeline, 2 CTAs/SM (80KB smem + <=128 regs per thread).
// ---------------------------------------------------------------------------
#define BM 128
#define BN 128
#define BK 32
#define PAD 40
#define ATILE (BM * PAD * 2)                 // 10240 B
#define BTILE (BN * PAD * 2)                 // 10240 B
#define STAGE (ATILE + BTILE)                // 20480 B
#define GEMM_SMEM (4 * STAGE)                // 81920 B

__global__ __launch_bounds__(256, 2) void hgemm(
    const __half* __restrict__ A, const __half* __restrict__ B,
    float* __restrict__ C, int Kdim, int Nstride) {
    extern __shared__ char sm[];
    uint32_t smb = smem_u32(sm);
    const int tid = threadIdx.x;
    const int lane = tid & 31, wid = tid >> 5;
    const int wm = (wid >> 2) * 64;          // 0 or 64
    const int wn = (wid & 3) * 32;           // 0..96

    const size_t mBase = (size_t)blockIdx.y * BM;
    const size_t nBase = (size_t)blockIdx.x * BN;
    const __half* Ag = A + mBase * Kdim;
    const __half* Bg = B + nBase * Kdim;

    auto load = [&](int buf, int kc) {
        uint32_t base = smb + buf * STAGE;
        #pragma unroll
        for (int j = 0; j < 4; j++) {
            int c = tid + j * 256;              // 0..1023
            if (c < 512) {
                int row = c >> 2, col = (c & 3) << 3;
                cp16(base + (row * PAD + col) * 2, Ag + (size_t)row * Kdim + kc + col);
            } else {
                int cc = c - 512;
                int row = cc >> 2, col = (cc & 3) << 3;
                cp16(base + ATILE + (row * PAD + col) * 2, Bg + (size_t)row * Kdim + kc + col);
            }
        }
    };

    float acc[4][4][4];
    #pragma unroll
    for (int i = 0; i < 4; i++)
        #pragma unroll
        for (int j = 0; j < 4; j++)
            #pragma unroll
            for (int e = 0; e < 4; e++) acc[i][j][e] = 0.f;

    const int t8 = lane >> 3, r8 = lane & 7;
    const int aRow = wm + r8 + ((t8 & 1) << 3);
    const int aCol = (t8 >> 1) << 3;
    const int bRow = wn + r8 + ((t8 >> 1) << 3);
    const int bCol = (t8 & 1) << 3;

    const int KITERS = Kdim / BK;
    load(0, 0); CP_COMMIT();
    load(1, BK); CP_COMMIT();
    load(2, 2 * BK); CP_COMMIT();

    for (int it = 0; it < KITERS; ++it) {
        int rem = KITERS - 1 - it;
        if (rem >= 2) { CP_WAIT2(); } else if (rem == 1) { CP_WAIT1(); } else { CP_WAIT0(); }
        __syncthreads();

        uint32_t base = smb + (it & 3) * STAGE;
        uint32_t sA = base, sB = base + ATILE;

        #pragma unroll
        for (int ks = 0; ks < 2; ks++) {
            int k0 = ks << 4;
            uint32_t a[4][4];
            #pragma unroll
            for (int mf = 0; mf < 4; mf++)
                ldm4(a[mf], sA + ((aRow + mf * 16) * PAD + k0 + aCol) * 2);
            uint32_t b[4][2];
            #pragma unroll
            for (int nf2 = 0; nf2 < 2; nf2++) {
                uint32_t r[4];
                ldm4(r, sB + ((bRow + nf2 * 16) * PAD + k0 + bCol) * 2);
                b[nf2 * 2][0] = r[0]; b[nf2 * 2][1] = r[1];
                b[nf2 * 2 + 1][0] = r[2]; b[nf2 * 2 + 1][1] = r[3];
            }
            #pragma unroll
            for (int mf = 0; mf < 4; mf++)
                #pragma unroll
                for (int nf = 0; nf < 4; nf++)
                    mma_f16(acc[mf][nf], a[mf], b[nf]);
        }
        if (it + 3 < KITERS) {
            load((it + 3) & 3, (it + 3) * BK);
            CP_COMMIT();
        }
    }

    float* Cb = C + (mBase + wm) * Nstride + nBase + wn;
    const int er = lane >> 2, ec = (lane & 3) * 2;
    #pragma unroll
    for (int mf = 0; mf < 4; mf++) {
        #pragma unroll
        for (int nf = 0; nf < 4; nf++) {
            float* p0 = Cb + (size_t)(mf * 16 + er) * Nstride + nf * 8 + ec;
            p0[0] = acc[mf][nf][0];
            p0[1] = acc[mf][nf][1];
            float* p1 = p0 + 8 * (size_t)Nstride;
            p1[0] = acc[mf][nf][2];
            p1[1] = acc[mf][nf][3];
        }
    }
}

// ---------------------------------------------------------------------------
// Kernel 4: head prep: optional per-head RMS + partial RoPE -> fp16,
// layout transform [tok][h][HD] -> [b][h][t][HD]. One warp per row.
// ---------------------------------------------------------------------------
__global__ __launch_bounds__(256) void head_prep(
    const float* __restrict__ src_base, int H, int src_off,
    const float* __restrict__ w, const float* __restrict__ tcos,
    const float* __restrict__ tsin, int do_norm, __half* __restrict__ dst) {
    int rowi = blockIdx.x * 8 + (threadIdx.x >> 5);
    int lane = threadIdx.x & 31;
    int h = rowi % H;
    int tok = rowi / H;
    int t = tok & (T_ - 1);
    int b = tok >> 11;

    const float* p = src_base + (size_t)tok * NQKV + src_off + h * HD_;
    float v[5];
    #pragma unroll
    for (int i = 0; i < 5; i++) v[i] = p[lane + 32 * i];

    if (do_norm) {
        float ss = 0.f;
        #pragma unroll
        for (int i = 0; i < 5; i++) ss += v[i] * v[i];
        #pragma unroll
        for (int m = 16; m; m >>= 1) ss += __shfl_xor_sync(0xffffffffu, ss, m);
        float r = rsqrtf(ss * (1.0f / (float)HD_) + EPS_);
        const float* wh = w + h * HD_;
        #pragma unroll
        for (int i = 0; i < 5; i++) v[i] *= r * wh[lane + 32 * i];
        {   // RoPE d = lane (0..31)
            float partner = __shfl_xor_sync(0xffffffffu, v[0], 1);
            float rot = (lane & 1) ? partner : -partner;
            v[0] = v[0] * tcos[t * RD_ + lane] + rot * tsin[t * RD_ + lane];
        }
        {   // RoPE d = 32..39
            float partner = __shfl_xor_sync(0xffffffffu, v[1], 1);
            if (lane < 8) {
                int d = 32 + lane;
                float rot = (lane & 1) ? partner : -partner;
                v[1] = v[1] * tcos[t * RD_ + d] + rot * tsin[t * RD_ + d];
            }
        }
    }
    size_t dbase = ((size_t)(b * H + h) * T_ + t) * HD_;
    #pragma unroll
    for (int i = 0; i < 5; i++)
        dst[dbase + lane + 32 * i] = __float2half_rn(v[i]);
}

// ---------------------------------------------------------------------------
// Kernel 5: fp16 HMMA causal flash attention (unchanged from R6).
// ---------------------------------------------------------------------------
#define ROWB 336                    // 168 halves * 2 bytes
#define FQ_SZ 43008                 // 128 * ROWB
#define FK_SZ 21504                 // 64 * ROWB
#define FKOFF FQ_SZ                 // K bufs
#define FVOFF (FQ_SZ + 2 * FK_SZ)   // V bufs
#define FLASH_SMEM (FQ_SZ + 4 * FK_SZ)   // 129024

__global__ __launch_bounds__(256, 1) void flash_hmma(
    const __half* __restrict__ Qf, const __half* __restrict__ Kf,
    const __half* __restrict__ Vf, __half* __restrict__ Of) {
    extern __shared__ char sm[];
    uint32_t smb = smem_u32(sm);
    const int qt = (T_ / 128 - 1) - blockIdx.x;   // heavy tiles first
    const int h = blockIdx.y, b = blockIdx.z;
    const int hk = h >> 2;
    const int tid = threadIdx.x, lane = tid & 31, wid = tid >> 5;

    const __half* Qg = Qf + ((size_t)(b * HQ_ + h) * T_ + qt * 128) * HD_;
    const __half* Kg = Kf + (size_t)(b * HK_ + hk) * T_ * HD_;
    const __half* Vg = Vf + (size_t)(b * HK_ + hk) * T_ * HD_;

    #pragma unroll
    for (int j = 0; j < 10; j++) {
        int c = tid + j * 256;
        int row = c / 20, col = (c % 20) * 8;
        cp16(smb + row * ROWB + col * 2, Qg + row * HD_ + col);
    }
    auto load_k = [&](int buf, int kt) {
        uint32_t base = smb + FKOFF + buf * FK_SZ;
        const __half* s = Kg + (size_t)kt * 64 * HD_;
        #pragma unroll
        for (int j = 0; j < 5; j++) {
            int c = tid + j * 256;
            int row = c / 20, col = (c % 20) * 8;
            cp16(base + row * ROWB + col * 2, s + row * HD_ + col);
        }
    };
    auto load_v = [&](int buf, int kt) {
        uint32_t base = smb + FVOFF + buf * FK_SZ;
        const __half* s = Vg + (size_t)kt * 64 * HD_;
        #pragma unroll
        for (int j = 0; j < 5; j++) {
            int c = tid + j * 256;
            int row = c / 20, col = (c % 20) * 8;
            cp16(base + row * ROWB + col * 2, s + row * HD_ + col);
        }
    };

    load_k(0, 0); CP_COMMIT();
    load_v(0, 0); CP_COMMIT();

    float m0 = -1e30f, m1 = -1e30f, l0 = 0.f, l1 = 0.f;
    float o[20][4];
    #pragma unroll
    for (int f = 0; f < 20; f++)
        #pragma unroll
        for (int e = 0; e < 4; e++) o[f][e] = 0.f;

    const int gr = lane >> 2, ct = lane & 3;
    const int ldrow = (lane & 7) + ((lane >> 3) & 1) * 8;
    const int ldcol = ((lane >> 4) & 1) * 8;
    const uint32_t q_b = smb + (wid * 16 + ldrow) * ROWB + ldcol * 2;
    const int rowg0 = qt * 128 + wid * 16 + gr;

    const int nkt = 2 * qt + 2;
    const float sc = 0.07905694150420949f * 1.4426950408889634f;  // scale*log2e

    for (int kt = 0; kt < nkt; kt++) {
        if (kt + 1 < nkt) {
            load_k((kt + 1) & 1, kt + 1); CP_COMMIT();
            load_v((kt + 1) & 1, kt + 1); CP_COMMIT();
            CP_WAIT2();
        } else {
            CP_WAIT0();
        }
        __syncthreads();

        // ---- S = Q K^T ----
        float s[8][4];
        #pragma unroll
        for (int f = 0; f < 8; f++)
            #pragma unroll
            for (int e = 0; e < 4; e++) s[f][e] = 0.f;

        uint32_t kb = smb + FKOFF + (kt & 1) * FK_SZ + ldrow * ROWB + ldcol * 2;
        #pragma unroll
        for (int ks = 0; ks < 10; ks++) {
            uint32_t a[4];
            ldm4(a, q_b + ks * 32);
            #pragma unroll
            for (int ng = 0; ng < 4; ng++) {
                uint32_t r[4];
                ldm4(r, kb + ng * 16 * ROWB + ks * 32);
                uint32_t b0[2] = {r[0], r[2]}, b1[2] = {r[1], r[3]};
                mma_f16(s[2 * ng], a, b0);
                mma_f16(s[2 * ng + 1], a, b1);
            }
        }

        // ---- mask + scale (base-2 domain) ----
        if (kt * 64 + 63 > qt * 128 + wid * 16) {
            #pragma unroll
            for (int f = 0; f < 8; f++) {
                int col = kt * 64 + f * 8 + 2 * ct;
                s[f][0] = (col     > rowg0)     ? -1e30f : s[f][0] * sc;
                s[f][1] = (col + 1 > rowg0)     ? -1e30f : s[f][1] * sc;
                s[f][2] = (col     > rowg0 + 8) ? -1e30f : s[f][2] * sc;
                s[f][3] = (col + 1 > rowg0 + 8) ? -1e30f : s[f][3] * sc;
            }
        } else {
            #pragma unroll
            for (int f = 0; f < 8; f++)
                #pragma unroll
                for (int e = 0; e < 4; e++) s[f][e] *= sc;
        }

        // ---- online softmax ----
        float r0 = -1e30f, r1 = -1e30f;
        #pragma unroll
        for (int f = 0; f < 8; f++) {
            r0 = fmaxf(r0, fmaxf(s[f][0], s[f][1]));
            r1 = fmaxf(r1, fmaxf(s[f][2], s[f][3]));
        }
        r0 = fmaxf(r0, __shfl_xor_sync(0xffffffffu, r0, 1));
        r0 = fmaxf(r0, __shfl_xor_sync(0xffffffffu, r0, 2));
        r1 = fmaxf(r1, __shfl_xor_sync(0xffffffffu, r1, 1));
        r1 = fmaxf(r1, __shfl_xor_sync(0xffffffffu, r1, 2));
        float mn0 = fmaxf(m0, r0), mn1 = fmaxf(m1, r1);
        float a0 = exp2p(m0 - mn0), a1 = exp2p(m1 - mn1);
        m0 = mn0; m1 = mn1;

        float rs0 = 0.f, rs1 = 0.f;
        uint32_t pA[8], pB[8];
        #pragma unroll
        for (int f = 0; f < 8; f++) {
            float p0 = exp2p(s[f][0] - mn0);
            float p1 = exp2p(s[f][1] - mn0);
            float p2 = exp2p(s[f][2] - mn1);
            float p3 = exp2p(s[f][3] - mn1);
            rs0 += p0 + p1; rs1 += p2 + p3;
            __half2 hA = __floats2half2_rn(p0, p1);
            __half2 hB = __floats2half2_rn(p2, p3);
            pA[f] = *(uint32_t*)&hA;
            pB[f] = *(uint32_t*)&hB;
        }
        rs0 += __shfl_xor_sync(0xffffffffu, rs0, 1);
        rs0 += __shfl_xor_sync(0xffffffffu, rs0, 2);
        rs1 += __shfl_xor_sync(0xffffffffu, rs1, 1);
        rs1 += __shfl_xor_sync(0xffffffffu, rs1, 2);
        l0 = l0 * a0 + rs0;
        l1 = l1 * a1 + rs1;
        #pragma unroll
        for (int f = 0; f < 20; f++) {
            o[f][0] *= a0; o[f][1] *= a0; o[f][2] *= a1; o[f][3] *= a1;
        }

        // ---- O += P V ----
        uint32_t vbase = smb + FVOFF + (kt & 1) * FK_SZ;
        #pragma unroll
        for (int ks = 0; ks < 4; ks++) {
            uint32_t a[4] = {pA[2 * ks], pB[2 * ks], pA[2 * ks + 1], pB[2 * ks + 1]};
            uint32_t vb = vbase + (ks * 16 + ldrow) * ROWB + ldcol * 2;
            #pragma unroll
            for (int nb = 0; nb < 10; nb++) {
                uint32_t r[4];
                ldm4t(r, vb + nb * 32);
                uint32_t b0[2] = {r[0], r[1]}, b1[2] = {r[2], r[3]};
                mma_f16(o[2 * nb], a, b0);
                mma_f16(o[2 * nb + 1], a, b1);
            }
        }
        __syncthreads();
    }

    // ---- epilogue ----
    float i0 = 1.f / l0, i1 = 1.f / l1;
    size_t rb0 = (size_t)(b * T_ + qt * 128 + wid * 16 + gr) * D_ + h * HD_;
    size_t rb1 = rb0 + 8 * (size_t)D_;
    #pragma unroll
    for (int f = 0; f < 20; f++) {
        int col = f * 8 + 2 * ct;
        __half2 h01 = __floats2half2_rn(o[f][0] * i0, o[f][1] * i0);
        __half2 h23 = __floats2half2_rn(o[f][2] * i1, o[f][3] * i1);
        *(uint32_t*)(Of + rb0 + col) = *(uint32_t*)&h01;
        *(uint32_t*)(Of + rb1 + col) = *(uint32_t*)&h23;
    }
}

// ---------------------------------------------------------------------------
// Host launch
// ---------------------------------------------------------------------------
extern "C" void kernel_launch(void* const* d_in, const int* in_sizes, int n_in,
                              void* d_out, int out_size) {
    const float* x      = (const float*)d_in[0];
    const float* wq     = (const float*)d_in[1];
    const float* wk     = (const float*)d_in[2];
    const float* wv     = (const float*)d_in[3];
    const float* wo     = (const float*)d_in[4];
    const float* norm_w = (const float*)d_in[5];
    const float* norm_b = (const float*)d_in[6];
    const float* qn_w   = (const float*)d_in[7];
    const float* kn_w   = (const float*)d_in[8];
    float* out = (float*)d_out;

    __half *af, *wtf, *wof, *of, *qf, *kf, *vf;
    float *qkv, *tcos, *tsin;
    cudaGetSymbolAddress((void**)&af,   g_af);
    cudaGetSymbolAddress((void**)&wtf,  g_wtf);
    cudaGetSymbolAddress((void**)&wof,  g_wof);
    cudaGetSymbolAddress((void**)&of,   g_of);
    cudaGetSymbolAddress((void**)&qf,   g_qf);
    cudaGetSymbolAddress((void**)&kf,   g_kf);
    cudaGetSymbolAddress((void**)&vf,   g_vf);
    cudaGetSymbolAddress((void**)&qkv,  g_qkv);
    cudaGetSymbolAddress((void**)&tcos, g_cos);
    cudaGetSymbolAddress((void**)&tsin, g_sin);

    cudaFuncSetAttribute(hgemm, cudaFuncAttributeMaxDynamicSharedMemorySize, GEMM_SMEM);
    cudaFuncSetAttribute(flash_hmma, cudaFuncAttributeMaxDynamicSharedMemorySize, FLASH_SMEM);

    // 0. fused weight transpose [wq|wk|wv] -> fp16
    wsplit_h<<<dim3(NQKV / 32, D_ / 32), 256>>>(wq, wk, wv, wtf);
    // 1. RMS layernorm -> fp16
    rmsnorm_kernel<<<NTOK, 256>>>(x, norm_w, norm_b, af);
    // 2. rope tables
    rope_table_kernel<<<(T_ * RD_ + 255) / 256, 256>>>(tcos, tsin);
    // 3. fused QKV projection (fp16 HMMA)
    hgemm<<<dim3(NQKV / BN, NTOK / BM), 256, GEMM_SMEM>>>(af, wtf, qkv, D_, NQKV);
    // 4. wo transpose -> fp16
    wsplit_h<<<dim3(D_ / 32, D_ / 32), 256>>>(wo, wo, wo, wof);
    // 5-7. head prep: q norm+rope, k norm+rope, v; layout [b][h][t][hd] fp16
    head_prep<<<(NTOK * HQ_) / 8, 256>>>(qkv, HQ_, 0,    qn_w, tcos, tsin, 1, qf);
    head_prep<<<(NTOK * HK_) / 8, 256>>>(qkv, HK_, KOFF, kn_w, tcos, tsin, 1, kf);
    head_prep<<<(NTOK * HK_) / 8, 256>>>(qkv, HK_, VOFF, kn_w, tcos, tsin, 0, vf);
    // 8. fp16 HMMA flash attention
    flash_hmma<<<dim3(T_ / 128, HQ_, B_), 256, FLASH_SMEM>>>(qf, kf, vf, of);
    // 9. output projection (fp16 HMMA)
    hgemm<<<dim3(D_ / BN, NTOK / BM), 256, GEMM_SMEM>>>(of, wof, out, D_, D_);
}